// round 9
// baseline (speedup 1.0000x reference)
#include <cuda_runtime.h>
#include <cuda_bf16.h>
#include <stdint.h>
#include <math.h>

typedef unsigned int u32;

#define BATCH 2
#define C 192
#define HH 256
#define WW 256
#define HW (HH*WW)
#define NPIX (BATCH*HW)
#define NH 8
#define HD 24
#define WS 8
#define SS 4
#define HID 510
#define HID2 1020

// ---- scratch ----
__device__ float g_xt[NPIX*C];
__device__ float g_x2[NPIX*C];
__device__ __nv_bfloat16 g_xnb[(size_t)NPIX*C];
__device__ __nv_bfloat16 g_qkvb[(size_t)NPIX*576];
__device__ __nv_bfloat16 g_attnb[(size_t)NPIX*C];
__device__ __nv_bfloat16 g_ynb[(size_t)NPIX*C];
__device__ __nv_bfloat16 g_y[(size_t)NPIX*HID2];
__device__ __nv_bfloat16 g_gg[(size_t)NPIX*512];
__device__ __nv_bfloat16 g_qkvw[576*C];
__device__ __nv_bfloat16 g_projw[C*C];
__device__ __nv_bfloat16 g_pinb[HID2*C];
__device__ __nv_bfloat16 g_poutb[C*512];

__device__ __forceinline__ u32 sptr(const void* p) {
    return (u32)__cvta_generic_to_shared(p);
}
__device__ __forceinline__ void cpa16(u32 dst, const void* src, bool full) {
    int sz = full ? 16 : 0;
    asm volatile("cp.async.cg.shared.global [%0], [%1], 16, %2;" :: "r"(dst), "l"(src), "r"(sz));
}
__device__ __forceinline__ void ldsm4(u32& r0, u32& r1, u32& r2, u32& r3, u32 a) {
    asm volatile("ldmatrix.sync.aligned.m8n8.x4.shared.b16 {%0,%1,%2,%3}, [%4];"
        : "=r"(r0), "=r"(r1), "=r"(r2), "=r"(r3) : "r"(a));
}
__device__ __forceinline__ void ldsm4t(u32& r0, u32& r1, u32& r2, u32& r3, u32 a) {
    asm volatile("ldmatrix.sync.aligned.m8n8.x4.trans.shared.b16 {%0,%1,%2,%3}, [%4];"
        : "=r"(r0), "=r"(r1), "=r"(r2), "=r"(r3) : "r"(a));
}
__device__ __forceinline__ void mma_bf16(float& c0, float& c1, float& c2, float& c3,
    u32 a0, u32 a1, u32 a2, u32 a3, u32 b0, u32 b1) {
    asm volatile("mma.sync.aligned.m16n8k16.row.col.f32.bf16.bf16.f32 "
        "{%0,%1,%2,%3}, {%4,%5,%6,%7}, {%8,%9}, {%0,%1,%2,%3};"
        : "+f"(c0), "+f"(c1), "+f"(c2), "+f"(c3)
        : "r"(a0), "r"(a1), "r"(a2), "r"(a3), "r"(b0), "r"(b1));
}
__device__ __forceinline__ u32 packbf(float a, float b) {
    __nv_bfloat162 t = __floats2bfloat162_rn(a, b);
    return *(u32*)&t;
}

// ================= merged weight convert ==================
__global__ void k_cvt_all(const float* __restrict__ qkvw, const float* __restrict__ projw,
                          const float* __restrict__ pinw, const float* __restrict__ poutw) {
    int i = blockIdx.x*256 + threadIdx.x;
    if (i < 576*C) {
        g_qkvw[i] = __float2bfloat16(qkvw[i]);
        return;
    }
    i -= 576*C;
    if (i < C*C) {
        g_projw[i] = __float2bfloat16(projw[i]);
        return;
    }
    i -= C*C;
    if (i < HID2*C) {
        g_pinb[i] = __float2bfloat16(pinw[i]);
        return;
    }
    i -= HID2*C;
    if (i < C*512) {
        int o = i >> 9;
        int k = i & 511;
        g_poutb[i] = __float2bfloat16(k < HID ? poutw[o*HID + k] : 0.f);
    }
}

// ================= K1: LN1 + transpose + window-permuted bf16 ==================
__global__ __launch_bounds__(256) void k_ln1(const float* __restrict__ x,
        const float* __restrict__ w, const float* __restrict__ b) {
    __shared__ float s[C*33];
    __shared__ float smu[32];
    __shared__ float srv[32];
    __shared__ int slot_s[32];
    int pix0 = blockIdx.x * 32;
    int bb = pix0 / HW;
    int hw0 = pix0 % HW;
    for (int e = threadIdx.x; e < C*32; e += 256) {
        int c = e >> 5;
        int p = e & 31;
        s[c*33 + p] = x[(size_t)(bb*C + c)*HW + hw0 + p];
    }
    __syncthreads();
    {
        int lane = threadIdx.x & 31;
        int warp = threadIdx.x >> 5;
        #pragma unroll
        for (int pp = 0; pp < 4; pp++) {
            int p = warp*4 + pp;
            float sum = 0.f;
            float sq = 0.f;
            #pragma unroll
            for (int i = 0; i < 6; i++) {
                float v = s[(lane + 32*i)*33 + p];
                sum += v;
                sq += v*v;
            }
            #pragma unroll
            for (int o = 16; o; o >>= 1) {
                sum += __shfl_xor_sync(0xffffffffu, sum, o);
                sq  += __shfl_xor_sync(0xffffffffu, sq, o);
            }
            if (lane == 0) {
                float mu = sum / C;
                smu[p] = mu;
                srv[p] = rsqrtf(sq / C - mu*mu + 1e-5f);
            }
        }
    }
    if (threadIdx.x < 32) {
        int p = threadIdx.x;
        int hw = hw0 + p;
        int r = hw >> 8;
        int cc = hw & 255;
        int sr = (r - SS + 256) & 255;
        int sc = (cc - SS + 256) & 255;
        slot_s[p] = (((bb << 10) + ((sr >> 3) << 5) + (sc >> 3)) << 6) + ((sr & 7) << 3) + (sc & 7);
    }
    __syncthreads();
    for (int e = threadIdx.x; e < C*32; e += 256) {
        int p = e / C;
        int c = e % C;
        float v = s[c*33 + p];
        g_xt[(pix0 + p)*C + c] = v;
        float ln = (v - smu[p]) * srv[p] * w[c] + b[c];
        g_xnb[(size_t)slot_s[p]*C + c] = __float2bfloat16(ln);
    }
}

// ================= shared B-tile loader for persistent-A GEMMs ==================
__device__ __forceinline__ void bpload(__nv_bfloat16* Bst, const __nv_bfloat16* W,
                                       int og0, int k0, int nlim, int tid) {
    #pragma unroll
    for (int i = 0; i < 2; i++) {
        int e = tid + i*256;
        int row = e >> 2;
        int seg = e & 3;
        int og = og0 + row;
        bool ok = og < nlim;
        cpa16(sptr(Bst + row*40 + seg*8), W + (size_t)(ok ? og : 0)*C + k0 + seg*8, ok);
    }
    asm volatile("cp.async.commit_group;" ::: "memory");
}

// ================= K2a: QKV GEMM, persistent A (131072 x 576 x 192) ==================
#define APAD 200
__global__ __launch_bounds__(256,2) void k_qkv_p() {
    extern __shared__ __nv_bfloat16 smq[];
    __nv_bfloat16* Ar = smq;               // 128 x 200
    __nv_bfloat16* Bs = smq + 128*APAD;    // 2 x 128*40
    int pt = blockIdx.x*128;
    int tid = threadIdx.x;
    int lane = tid & 31;
    int warp = tid >> 5;
    int m0 = (warp >> 2)*64;
    int n0 = (warp & 3)*32;

    #pragma unroll
    for (int i = 0; i < 12; i++) {
        int e = tid + i*256;
        int row = e / 24;
        int seg = e - row*24;
        cpa16(sptr(Ar + row*APAD + seg*8), g_xnb + (size_t)(pt + row)*C + seg*8, true);
    }
    asm volatile("cp.async.commit_group;" ::: "memory");
    bpload(Bs, g_qkvw, 0, 0, 576, tid);
    asm volatile("cp.async.wait_group 0;" ::: "memory");
    __syncthreads();

    const float qscale = 0.20412414523193154f;
    int lr = lane >> 2;
    int lc = lane & 3;
    u32 arb = sptr(Ar);

    for (int ot = 0; ot < 5; ot++) {
        float acc[4][4][4] = {};
        for (int ch = 0; ch < 6; ch++) {
            int it = ot*6 + ch;
            if (it > 0) {
                asm volatile("cp.async.wait_group 0;" ::: "memory");
                __syncthreads();
            }
            int it2 = it + 1;
            if (it2 < 30) {
                int ot2 = it2 / 6;
                int ch2 = it2 - ot2*6;
                bpload(Bs + (it2 & 1)*5120, g_qkvw, ot2*128, ch2*32, 576, tid);
            }
            u32 bbs = sptr(Bs + (it & 1)*5120);
            #pragma unroll
            for (int ks = 0; ks < 2; ks++) {
                u32 av[4][4];
                u32 bv[4][2];
                #pragma unroll
                for (int mt = 0; mt < 4; mt++) {
                    int row = m0 + mt*16 + (lane & 15);
                    u32 ad = arb + (row*APAD + ch*32 + ((lane >> 4) & 1)*8 + ks*16)*2;
                    ldsm4(av[mt][0], av[mt][1], av[mt][2], av[mt][3], ad);
                }
                #pragma unroll
                for (int n2 = 0; n2 < 2; n2++) {
                    int row = n0 + n2*16 + (lane & 7) + ((lane >> 4) & 1)*8;
                    u32 ad = bbs + (row*40 + ((lane >> 3) & 1)*8 + ks*16)*2;
                    u32 r0;
                    u32 r1;
                    u32 r2;
                    u32 r3;
                    ldsm4(r0, r1, r2, r3, ad);
                    bv[n2*2+0][0] = r0;
                    bv[n2*2+0][1] = r1;
                    bv[n2*2+1][0] = r2;
                    bv[n2*2+1][1] = r3;
                }
                #pragma unroll
                for (int mt = 0; mt < 4; mt++) {
                    #pragma unroll
                    for (int nt = 0; nt < 4; nt++) {
                        mma_bf16(acc[mt][nt][0], acc[mt][nt][1], acc[mt][nt][2], acc[mt][nt][3],
                                 av[mt][0], av[mt][1], av[mt][2], av[mt][3], bv[nt][0], bv[nt][1]);
                    }
                }
            }
        }
        #pragma unroll
        for (int mt = 0; mt < 4; mt++) {
            int row = pt + m0 + mt*16 + lr;
            #pragma unroll
            for (int nt = 0; nt < 4; nt++) {
                int col = ot*128 + n0 + nt*8 + 2*lc;
                if (col < 576) {
                    float s = (col < C) ? qscale : 1.f;
                    __nv_bfloat162 v0;
                    v0.x = __float2bfloat16(acc[mt][nt][0] * s);
                    v0.y = __float2bfloat16(acc[mt][nt][1] * s);
                    *(__nv_bfloat162*)&g_qkvb[(size_t)row*576 + col] = v0;
                    __nv_bfloat162 v1;
                    v1.x = __float2bfloat16(acc[mt][nt][2] * s);
                    v1.y = __float2bfloat16(acc[mt][nt][3] * s);
                    *(__nv_bfloat162*)&g_qkvb[(size_t)(row+8)*576 + col] = v1;
                }
            }
        }
    }
}

// ================= K2b: tensor-core window attention ==================
#define SW 776
__global__ __launch_bounds__(128,2) void k_wattn_t(const float* __restrict__ rpb) {
    extern __shared__ __nv_bfloat16 smw[];
    __shared__ float rpb_s[225*NH];
    __shared__ int lab[64];

    int tid = threadIdx.x;
    int lane = tid & 31;
    int warp = tid >> 5;
    int widx = blockIdx.x;
    int pix0 = widx * 64;
    int wy = (widx >> 5) & 31;
    int wx = widx & 31;

    if (tid < 64) {
        int i1 = tid >> 3;
        int j1 = tid & 7;
        int sr = wy*8 + i1;
        int sc = wx*8 + j1;
        lab[tid] = ((sr >= HH-WS) + (sr >= HH-SS))*3 + ((sc >= WW-WS) + (sc >= WW-SS));
    }
    for (int e = tid; e < 225*NH; e += 128) {
        rpb_s[e] = rpb[e];
    }
    for (int e = tid; e < 1024; e += 128) {
        int row = e >> 4;
        int reg = e & 15;
        int col = (reg < 8) ? (reg*32 + 24) : (256 + (reg - 8)*32 + 24);
        *(float4*)&smw[row*SW + col] = make_float4(0.f, 0.f, 0.f, 0.f);
    }
    for (int e = tid; e < 4608; e += 128) {
        int row = e / 72;
        int t = e - row*72;
        int sec = t / 24;
        int t2 = t - sec*24;
        int h = t2 / 3;
        int cs = (t2 - h*3)*8;
        int srccol = sec*192 + h*24 + cs;
        int dstcol = sec*256 + h*32 + cs;
        cpa16(sptr(&smw[row*SW + dstcol]), g_qkvb + (size_t)(pix0 + row)*576 + srccol, true);
    }
    asm volatile("cp.async.commit_group;" ::: "memory");
    asm volatile("cp.async.wait_group 0;" ::: "memory");
    __syncthreads();

    int lr = lane >> 2;
    int lc = lane & 3;
    int wrow0 = warp*16;
    int r0 = wrow0 + lr;
    int r1 = r0 + 8;
    int baseA = (((r0 >> 3) + 7)*15 + ((r0 & 7) - 2*lc + 7))*8;
    int baseB = (((r1 >> 3) + 7)*15 + ((r1 & 7) - 2*lc + 7))*8;
    int labA = lab[r0];
    int labB = lab[r1];
    u32 mbits = 0;
    #pragma unroll
    for (int f = 0; f < 8; f++) {
        int cA = f*8 + 2*lc;
        int lA = lab[cA];
        int lB = lab[cA + 1];
        if (labA != lA) { mbits |= 1u << (f*4 + 0); }
        if (labA != lB) { mbits |= 1u << (f*4 + 1); }
        if (labB != lA) { mbits |= 1u << (f*4 + 2); }
        if (labB != lB) { mbits |= 1u << (f*4 + 3); }
    }

    u32 smbase = sptr(smw);
    for (int h = 0; h < NH; h++) {
        float c[8][4];
        #pragma unroll
        for (int f = 0; f < 8; f++) {
            c[f][0] = 0.f; c[f][1] = 0.f; c[f][2] = 0.f; c[f][3] = 0.f;
        }
        #pragma unroll
        for (int ks = 0; ks < 2; ks++) {
            u32 aq[4];
            u32 ad = smbase + ((wrow0 + (lane & 15))*SW + h*32 + ((lane >> 4) & 1)*8 + ks*16)*2;
            ldsm4(aq[0], aq[1], aq[2], aq[3], ad);
            #pragma unroll
            for (int n2 = 0; n2 < 4; n2++) {
                u32 b0;
                u32 b1;
                u32 b2;
                u32 b3;
                u32 bd = smbase + ((n2*16 + (lane & 7) + ((lane >> 4) & 1)*8)*SW
                                   + 256 + h*32 + ((lane >> 3) & 1)*8 + ks*16)*2;
                ldsm4(b0, b1, b2, b3, bd);
                mma_bf16(c[2*n2][0], c[2*n2][1], c[2*n2][2], c[2*n2][3],
                         aq[0], aq[1], aq[2], aq[3], b0, b1);
                mma_bf16(c[2*n2+1][0], c[2*n2+1][1], c[2*n2+1][2], c[2*n2+1][3],
                         aq[0], aq[1], aq[2], aq[3], b2, b3);
            }
        }
        int hA = baseA + h;
        int hB = baseB + h;
        #pragma unroll
        for (int f = 0; f < 8; f++) {
            c[f][0] += rpb_s[hA - 120*f]     + (((mbits >> (f*4+0)) & 1) ? -100.f : 0.f);
            c[f][1] += rpb_s[hA - 120*f - 8] + (((mbits >> (f*4+1)) & 1) ? -100.f : 0.f);
            c[f][2] += rpb_s[hB - 120*f]     + (((mbits >> (f*4+2)) & 1) ? -100.f : 0.f);
            c[f][3] += rpb_s[hB - 120*f - 8] + (((mbits >> (f*4+3)) & 1) ? -100.f : 0.f);
        }
        float mx0 = -1e30f;
        float mx1 = -1e30f;
        #pragma unroll
        for (int f = 0; f < 8; f++) {
            mx0 = fmaxf(mx0, fmaxf(c[f][0], c[f][1]));
            mx1 = fmaxf(mx1, fmaxf(c[f][2], c[f][3]));
        }
        mx0 = fmaxf(mx0, __shfl_xor_sync(0xffffffffu, mx0, 1));
        mx0 = fmaxf(mx0, __shfl_xor_sync(0xffffffffu, mx0, 2));
        mx1 = fmaxf(mx1, __shfl_xor_sync(0xffffffffu, mx1, 1));
        mx1 = fmaxf(mx1, __shfl_xor_sync(0xffffffffu, mx1, 2));
        float s0 = 0.f;
        float s1 = 0.f;
        #pragma unroll
        for (int f = 0; f < 8; f++) {
            c[f][0] = __expf(c[f][0] - mx0);
            c[f][1] = __expf(c[f][1] - mx0);
            c[f][2] = __expf(c[f][2] - mx1);
            c[f][3] = __expf(c[f][3] - mx1);
            s0 += c[f][0] + c[f][1];
            s1 += c[f][2] + c[f][3];
        }
        s0 += __shfl_xor_sync(0xffffffffu, s0, 1);
        s0 += __shfl_xor_sync(0xffffffffu, s0, 2);
        s1 += __shfl_xor_sync(0xffffffffu, s1, 1);
        s1 += __shfl_xor_sync(0xffffffffu, s1, 2);
        float inv0 = 1.f / s0;
        float inv1 = 1.f / s1;
        u32 ap[4][4];
        #pragma unroll
        for (int j = 0; j < 4; j++) {
            ap[j][0] = packbf(c[2*j][0]*inv0,   c[2*j][1]*inv0);
            ap[j][1] = packbf(c[2*j][2]*inv1,   c[2*j][3]*inv1);
            ap[j][2] = packbf(c[2*j+1][0]*inv0, c[2*j+1][1]*inv0);
            ap[j][3] = packbf(c[2*j+1][2]*inv1, c[2*j+1][3]*inv1);
        }
        float o[3][4];
        #pragma unroll
        for (int nt = 0; nt < 3; nt++) {
            o[nt][0] = 0.f; o[nt][1] = 0.f; o[nt][2] = 0.f; o[nt][3] = 0.f;
        }
        #pragma unroll
        for (int j = 0; j < 4; j++) {
            u32 lo0; u32 lo1; u32 lo2; u32 lo3;
            u32 hi0; u32 hi1; u32 hi2; u32 hi3;
            u32 vlo = smbase + ((j*16 + (lane & 7))*SW + 512 + h*32 + (lane >> 3)*8)*2;
            u32 vhi = smbase + ((j*16 + 8 + (lane & 7))*SW + 512 + h*32 + (lane >> 3)*8)*2;
            ldsm4t(lo0, lo1, lo2, lo3, vlo);
            ldsm4t(hi0, hi1, hi2, hi3, vhi);
            mma_bf16(o[0][0], o[0][1], o[0][2], o[0][3], ap[j][0], ap[j][1], ap[j][2], ap[j][3], lo0, hi0);
            mma_bf16(o[1][0], o[1][1], o[1][2], o[1][3], ap[j][0], ap[j][1], ap[j][2], ap[j][3], lo1, hi1);
            mma_bf16(o[2][0], o[2][1], o[2][2], o[2][3], ap[j][0], ap[j][1], ap[j][2], ap[j][3], lo2, hi2);
        }
        #pragma unroll
        for (int nt = 0; nt < 3; nt++) {
            int col = h*24 + nt*8 + 2*lc;
            __nv_bfloat162 v0;
            v0.x = __float2bfloat16(o[nt][0]);
            v0.y = __float2bfloat16(o[nt][1]);
            *(__nv_bfloat162*)&g_attnb[(size_t)(pix0 + r0)*C + col] = v0;
            __nv_bfloat162 v1;
            v1.x = __float2bfloat16(o[nt][2]);
            v1.y = __float2bfloat16(o[nt][3]);
            *(__nv_bfloat162*)&g_attnb[(size_t)(pix0 + r1)*C + col] = v1;
        }
    }
}

// ================= K2c: proj GEMM bf16 + bias + residual ==================
__device__ __forceinline__ void proj_load(__nv_bfloat16* Adst, __nv_bfloat16* Bdst,
                                          int pt, int ct, int k0, int tid) {
    #pragma unroll
    for (int i = 0; i < 2; i++) {
        int e = tid + i*256;
        int row = e >> 2;
        int seg = e & 3;
        cpa16(sptr(Adst + row*40 + seg*8), g_attnb + (size_t)(pt + row)*C + k0 + seg*8, true);
    }
    int row = tid >> 2;
    int seg = tid & 3;
    cpa16(sptr(Bdst + row*40 + seg*8), g_projw + (size_t)(ct + row)*C + k0 + seg*8, true);
    asm volatile("cp.async.commit_group;" ::: "memory");
}

__global__ __launch_bounds__(256,2) void k_proj_b(const float* __restrict__ pb) {
    __shared__ __align__(16) __nv_bfloat16 As[2][5120];
    __shared__ __align__(16) __nv_bfloat16 Bs[2][2560];
    int pt = blockIdx.y*128;
    int ct = blockIdx.x*64;
    int tid = threadIdx.x;
    int lane = tid & 31;
    int warp = tid >> 5;
    int m0 = (warp & 3)*32;
    int n0 = (warp >> 2)*32;
    float acc[2][4][4] = {};

    proj_load(As[0], Bs[0], pt, ct, 0, tid);

    for (int ch = 0; ch < 6; ch++) {
        asm volatile("cp.async.wait_group 0;" ::: "memory");
        __syncthreads();
        if (ch < 5) {
            proj_load(As[(ch+1)&1], Bs[(ch+1)&1], pt, ct, (ch+1)*32, tid);
        }
        u32 ab = sptr(As[ch & 1]);
        u32 bbs = sptr(Bs[ch & 1]);
        #pragma unroll
        for (int ks = 0; ks < 2; ks++) {
            u32 av[2][4];
            u32 bv[4][2];
            #pragma unroll
            for (int mt = 0; mt < 2; mt++) {
                int row = m0 + mt*16 + (lane & 15);
                u32 ad = ab + (row*40 + ((lane >> 4) & 1)*8 + ks*16)*2;
                ldsm4(av[mt][0], av[mt][1], av[mt][2], av[mt][3], ad);
            }
            #pragma unroll
            for (int n2 = 0; n2 < 2; n2++) {
                int row = n0 + n2*16 + (lane & 7) + ((lane >> 4) & 1)*8;
                u32 ad = bbs + (row*40 + ((lane >> 3) & 1)*8 + ks*16)*2;
                u32 r0;
                u32 r1;
                u32 r2;
                u32 r3;
                ldsm4(r0, r1, r2, r3, ad);
                bv[n2*2+0][0] = r0;
                bv[n2*2+0][1] = r1;
                bv[n2*2+1][0] = r2;
                bv[n2*2+1][1] = r3;
            }
            #pragma unroll
            for (int mt = 0; mt < 2; mt++) {
                #pragma unroll
                for (int nt = 0; nt < 4; nt++) {
                    mma_bf16(acc[mt][nt][0], acc[mt][nt][1], acc[mt][nt][2], acc[mt][nt][3],
                             av[mt][0], av[mt][1], av[mt][2], av[mt][3], bv[nt][0], bv[nt][1]);
                }
            }
        }
    }

    int lr = lane >> 2;
    int lc = lane & 3;
    #pragma unroll
    for (int mt = 0; mt < 2; mt++) {
        #pragma unroll
        for (int half = 0; half < 2; half++) {
            int row = pt + m0 + mt*16 + lr + half*8;
            int bb = row >> 16;
            int widx = (row >> 6) & 1023;
            int tok = row & 63;
            int r = (((widx >> 5) << 3) + (tok >> 3) + SS) & 255;
            int c2 = (((widx & 31) << 3) + (tok & 7) + SS) & 255;
            int gbase = ((bb*HH + r)*WW + c2)*C;
            #pragma unroll
            for (int nt = 0; nt < 4; nt++) {
                int col = ct + n0 + nt*8 + 2*lc;
                float2 v;
                v.x = acc[mt][nt][half*2+0] + pb[col] + g_xt[gbase + col];
                v.y = acc[mt][nt][half*2+1] + pb[col+1] + g_xt[gbase + col + 1];
                *(float2*)&g_x2[gbase + col] = v;
            }
        }
    }
}

// ================= K3: LN2 -> bf16 ==================
__global__ __launch_bounds__(256) void k_ln2(const float* __restrict__ w,
                                             const float* __restrict__ b) {
    int pix = blockIdx.x*8 + (threadIdx.x >> 5);
    int lane = threadIdx.x & 31;
    const float* row = g_x2 + (size_t)pix*C;
    float v[6];
    float sum = 0.f;
    float sq = 0.f;
    #pragma unroll
    for (int i = 0; i < 6; i++) {
        v[i] = row[lane + 32*i];
        sum += v[i];
        sq += v[i]*v[i];
    }
    #pragma unroll
    for (int o = 16; o; o >>= 1) {
        sum += __shfl_xor_sync(0xffffffffu, sum, o);
        sq  += __shfl_xor_sync(0xffffffffu, sq, o);
    }
    float mu = sum / C;
    float rv = rsqrtf(sq / C - mu*mu + 1e-5f);
    __nv_bfloat16* outp = g_ynb + (size_t)pix*C;
    #pragma unroll
    for (int i = 0; i < 6; i++) {
        int c = lane + 32*i;
        outp[c] = __float2bfloat16((v[i]-mu)*rv*w[c] + b[c]);
    }
}

// ================= K4: pin GEMM, persistent A (131072 x 1020 x 192) ==================
__global__ __launch_bounds__(256,2) void k_pin_p() {
    extern __shared__ __nv_bfloat16 smp[];
    __nv_bfloat16* Ar = smp;
    __nv_bfloat16* Bs = smp + 128*APAD;
    int pt = blockIdx.x*128;
    int tid = threadIdx.x;
    int lane = tid & 31;
    int warp = tid >> 5;
    int m0 = (warp >> 2)*64;
    int n0 = (warp & 3)*32;

    #pragma unroll
    for (int i = 0; i < 12; i++) {
        int e = tid + i*256;
        int row = e / 24;
        int seg = e - row*24;
        cpa16(sptr(Ar + row*APAD + seg*8), g_ynb + (size_t)(pt + row)*C + seg*8, true);
    }
    asm volatile("cp.async.commit_group;" ::: "memory");
    bpload(Bs, g_pinb, 0, 0, HID2, tid);
    asm volatile("cp.async.wait_group 0;" ::: "memory");
    __syncthreads();

    int lr = lane >> 2;
    int lc = lane & 3;
    u32 arb = sptr(Ar);

    for (int ot = 0; ot < 8; ot++) {
        float acc[4][4][4] = {};
        for (int ch = 0; ch < 6; ch++) {
            int it = ot*6 + ch;
            if (it > 0) {
                asm volatile("cp.async.wait_group 0;" ::: "memory");
                __syncthreads();
            }
            int it2 = it + 1;
            if (it2 < 48) {
                int ot2 = it2 / 6;
                int ch2 = it2 - ot2*6;
                bpload(Bs + (it2 & 1)*5120, g_pinb, ot2*128, ch2*32, HID2, tid);
            }
            u32 bbs = sptr(Bs + (it & 1)*5120);
            #pragma unroll
            for (int ks = 0; ks < 2; ks++) {
                u32 av[4][4];
                u32 bv[4][2];
                #pragma unroll
                for (int mt = 0; mt < 4; mt++) {
                    int row = m0 + mt*16 + (lane & 15);
                    u32 ad = arb + (row*APAD + ch*32 + ((lane >> 4) & 1)*8 + ks*16)*2;
                    ldsm4(av[mt][0], av[mt][1], av[mt][2], av[mt][3], ad);
                }
                #pragma unroll
                for (int n2 = 0; n2 < 2; n2++) {
                    int row = n0 + n2*16 + (lane & 7) + ((lane >> 4) & 1)*8;
                    u32 ad = bbs + (row*40 + ((lane >> 3) & 1)*8 + ks*16)*2;
                    u32 r0;
                    u32 r1;
                    u32 r2;
                    u32 r3;
                    ldsm4(r0, r1, r2, r3, ad);
                    bv[n2*2+0][0] = r0;
                    bv[n2*2+0][1] = r1;
                    bv[n2*2+1][0] = r2;
                    bv[n2*2+1][1] = r3;
                }
                #pragma unroll
                for (int mt = 0; mt < 4; mt++) {
                    #pragma unroll
                    for (int nt = 0; nt < 4; nt++) {
                        mma_bf16(acc[mt][nt][0], acc[mt][nt][1], acc[mt][nt][2], acc[mt][nt][3],
                                 av[mt][0], av[mt][1], av[mt][2], av[mt][3], bv[nt][0], bv[nt][1]);
                    }
                }
            }
        }
        #pragma unroll
        for (int mt = 0; mt < 4; mt++) {
            int row = pt + m0 + mt*16 + lr;
            #pragma unroll
            for (int nt = 0; nt < 4; nt++) {
                int col = ot*128 + n0 + nt*8 + 2*lc;
                if (col < HID2) {
                    __nv_bfloat162 v0;
                    v0.x = __float2bfloat16(acc[mt][nt][0]);
                    v0.y = __float2bfloat16(acc[mt][nt][1]);
                    *(__nv_bfloat162*)&g_y[(size_t)row*HID2 + col] = v0;
                    __nv_bfloat162 v1;
                    v1.x = __float2bfloat16(acc[mt][nt][2]);
                    v1.y = __float2bfloat16(acc[mt][nt][3]);
                    *(__nv_bfloat162*)&g_y[(size_t)(row+8)*HID2 + col] = v1;
                }
            }
        }
    }
}

// ================= K5: depthwise 3x3 + gated GELU (bf162-vectorized) ==================
__global__ __launch_bounds__(256) void k_dw2(const float* __restrict__ dw) {
    int bx = blockIdx.x;
    int t = threadIdx.x;
    int xseg = (bx & 63) * 4;
    int r = (bx >> 6) & 255;
    int bb = bx >> 14;
    size_t prow = (size_t)(bb*HH + r)*WW;
    if (t >= 255) {
        if (t == 255) {
            #pragma unroll
            for (int o = 0; o < 4; o++) {
                *(u32*)&g_gg[(prow + xseg + o)*512 + 510] = 0u;
            }
        }
        return;
    }
    int c = t*2;
    float a0[3][6];
    float a1[3][6];
    float b0[3][6];
    float b1[3][6];
    #pragma unroll
    for (int dy = 0; dy < 3; dy++) {
        int rowi = r + dy - 1;
        bool rok = (unsigned)rowi < 256u;
        #pragma unroll
        for (int dx = 0; dx < 6; dx++) {
            int col = xseg + dx - 1;
            bool ok = rok && ((unsigned)col < 256u);
            float2 va = make_float2(0.f, 0.f);
            float2 vb = make_float2(0.f, 0.f);
            if (ok) {
                size_t base = ((size_t)(bb*HH + rowi)*WW + col)*HID2;
                va = __bfloat1622float2(*(const __nv_bfloat162*)&g_y[base + c]);
                vb = __bfloat1622float2(*(const __nv_bfloat162*)&g_y[base + c + HID]);
            }
            a0[dy][dx] = va.x;
            a1[dy][dx] = va.y;
            b0[dy][dx] = vb.x;
            b1[dy][dx] = vb.y;
        }
    }
    float wa0[9];
    float wa1[9];
    float wb0[9];
    float wb1[9];
    #pragma unroll
    for (int q = 0; q < 9; q++) {
        wa0[q] = dw[c*9 + q];
        wa1[q] = dw[(c+1)*9 + q];
        wb0[q] = dw[(c+HID)*9 + q];
        wb1[q] = dw[(c+HID+1)*9 + q];
    }
    #pragma unroll
    for (int o = 0; o < 4; o++) {
        float s0 = 0.f;
        float s1 = 0.f;
        float g0 = 0.f;
        float g1 = 0.f;
        #pragma unroll
        for (int ky = 0; ky < 3; ky++) {
            #pragma unroll
            for (int kx = 0; kx < 3; kx++) {
                int q = ky*3 + kx;
                s0 += wa0[q]*a0[ky][o+kx];
                s1 += wa1[q]*a1[ky][o+kx];
                g0 += wb0[q]*b0[ky][o+kx];
                g1 += wb1[q]*b1[ky][o+kx];
            }
        }
        float e0 = 0.5f*s0*(1.f + erff(s0*0.70710678118654752f)) * g0;
        float e1 = 0.5f*s1*(1.f + erff(s1*0.70710678118654752f)) * g1;
        *(__nv_bfloat162*)&g_gg[(prow + xseg + o)*512 + c] = __floats2bfloat162_rn(e0, e1);
    }
}

// ================= K6: pout GEMM bf16 + residual -> NCHW ==================
__device__ __forceinline__ void pout_load(__nv_bfloat16* Adst, __nv_bfloat16* Bdst,
                                          int pt, int ct, int k0, int tid) {
    #pragma unroll
    for (int i = 0; i < 2; i++) {
        int e = tid + i*256;
        int row = e >> 2;
        int seg = e & 3;
        cpa16(sptr(Adst + row*40 + seg*8), g_gg + (size_t)(pt + row)*512 + k0 + seg*8, true);
    }
    int row = tid >> 2;
    int seg = tid & 3;
    cpa16(sptr(Bdst + row*40 + seg*8), g_poutb + (size_t)(ct + row)*512 + k0 + seg*8, true);
    asm volatile("cp.async.commit_group;" ::: "memory");
}

#define SPP 132
__global__ __launch_bounds__(256,2) void k_pout_b(float* __restrict__ outp) {
    __shared__ __align__(16) float smem_f[8448];
    __nv_bfloat16* As = (__nv_bfloat16*)smem_f;
    __nv_bfloat16* Bs = (__nv_bfloat16*)(smem_f + 5120);
    float* Cs = smem_f;
    int pt = blockIdx.y*128;
    int ct = blockIdx.x*64;
    int tid = threadIdx.x;
    int lane = tid & 31;
    int warp = tid >> 5;
    int m0 = (warp & 3)*32;
    int n0 = (warp >> 2)*32;
    float acc[2][4][4] = {};

    pout_load(As, Bs, pt, ct, 0, tid);

    for (int ch = 0; ch < 16; ch++) {
        asm volatile("cp.async.wait_group 0;" ::: "memory");
        __syncthreads();
        if (ch < 15) {
            int st = (ch+1) & 1;
            pout_load(As + st*5120, Bs + st*2560, pt, ct, (ch+1)*32, tid);
        }
        u32 ab = sptr(As + (ch & 1)*5120);
        u32 bbs = sptr(Bs + (ch & 1)*2560);
        #pragma unroll
        for (int ks = 0; ks < 2; ks++) {
            u32 av[2][4];
            u32 bv[4][2];
            #pragma unroll
            for (int mt = 0; mt < 2; mt++) {
                int row = m0 + mt*16 + (lane & 15);
                u32 ad = ab + (row*40 + ((lane >> 4) & 1)*8 + ks*16)*2;
                ldsm4(av[mt][0], av[mt][1], av[mt][2], av[mt][3], ad);
            }
            #pragma unroll
            for (int n2 = 0; n2 < 2; n2++) {
                int row = n0 + n2*16 + (lane & 7) + ((lane >> 4) & 1)*8;
                u32 ad = bbs + (row*40 + ((lane >> 3) & 1)*8 + ks*16)*2;
                u32 r0;
                u32 r1;
                u32 r2;
                u32 r3;
                ldsm4(r0, r1, r2, r3, ad);
                bv[n2*2+0][0] = r0;
                bv[n2*2+0][1] = r1;
                bv[n2*2+1][0] = r2;
                bv[n2*2+1][1] = r3;
            }
            #pragma unroll
            for (int mt = 0; mt < 2; mt++) {
                #pragma unroll
                for (int nt = 0; nt < 4; nt++) {
                    mma_bf16(acc[mt][nt][0], acc[mt][nt][1], acc[mt][nt][2], acc[mt][nt][3],
                             av[mt][0], av[mt][1], av[mt][2], av[mt][3], bv[nt][0], bv[nt][1]);
                }
            }
        }
    }
    __syncthreads();

    int lr = lane >> 2;
    int lc = lane & 3;
    #pragma unroll
    for (int mt = 0; mt < 2; mt++) {
        int row = m0 + mt*16 + lr;
        #pragma unroll
        for (int nt = 0; nt < 4; nt++) {
            int col = n0 + nt*8 + 2*lc;
            Cs[col*SPP + row] = acc[mt][nt][0];
            Cs[(col+1)*SPP + row] = acc[mt][nt][1];
            Cs[col*SPP + row + 8] = acc[mt][nt][2];
            Cs[(col+1)*SPP + row + 8] = acc[mt][nt][3];
        }
    }
    __syncthreads();
    for (int e = tid; e < 2048; e += 256) {
        int p = e >> 4;
        int c4 = e & 15;
        float4 v = *(const float4*)&g_x2[(size_t)(pt + p)*C + ct + c4*4];
        Cs[(c4*4+0)*SPP + p] += v.x;
        Cs[(c4*4+1)*SPP + p] += v.y;
        Cs[(c4*4+2)*SPP + p] += v.z;
        Cs[(c4*4+3)*SPP + p] += v.w;
    }
    __syncthreads();
    int bb = pt >> 16;
    int hw0 = pt & 65535;
    for (int e = tid; e < 2048; e += 256) {
        int c = e >> 5;
        int p4 = e & 31;
        float4 v = *(const float4*)&Cs[c*SPP + p4*4];
        *(float4*)&outp[((size_t)(bb*C + ct + c))*HW + hw0 + p4*4] = v;
    }
}

// ================= launch ==================
extern "C" void kernel_launch(void* const* d_in, const int* in_sizes, int n_in,
                              void* d_out, int out_size) {
    const float* x      = (const float*)d_in[0];
    const float* n1w    = (const float*)d_in[1];
    const float* n1b    = (const float*)d_in[2];
    const float* qkv_w  = (const float*)d_in[3];
    const float* rpb    = (const float*)d_in[4];
    const float* proj_w = (const float*)d_in[5];
    const float* proj_b = (const float*)d_in[6];
    const float* n2w    = (const float*)d_in[7];
    const float* n2b    = (const float*)d_in[8];
    const float* pin_w  = (const float*)d_in[9];
    const float* dw_w   = (const float*)d_in[10];
    const float* pout_w = (const float*)d_in[11];
    float* outp = (float*)d_out;

    const int wattn_smem = 64*SW*2;                       // 99328
    const int pers_smem  = (128*APAD + 2*128*40)*2;       // 71680
    cudaFuncSetAttribute(k_wattn_t, cudaFuncAttributeMaxDynamicSharedMemorySize, wattn_smem);
    cudaFuncSetAttribute(k_qkv_p, cudaFuncAttributeMaxDynamicSharedMemorySize, pers_smem);
    cudaFuncSetAttribute(k_pin_p, cudaFuncAttributeMaxDynamicSharedMemorySize, pers_smem);

    const int cvt_total = 576*C + C*C + HID2*C + C*512;
    k_cvt_all<<<(cvt_total + 255)/256, 256>>>(qkv_w, proj_w, pin_w, pout_w);
    k_ln1    <<<NPIX/32, 256>>>(x, n1w, n1b);
    k_qkv_p  <<<NPIX/128, 256, pers_smem>>>();
    k_wattn_t<<<2048, 128, wattn_smem>>>(rpb);
    k_proj_b <<<dim3(3, NPIX/128), 256>>>(proj_b);
    k_ln2    <<<NPIX/8, 256>>>(n2w, n2b);
    k_pin_p  <<<NPIX/128, 256, pers_smem>>>();
    k_dw2    <<<BATCH*HH*(WW/4), 256>>>(dw_w);
    k_pout_b <<<dim3(3, NPIX/128), 256>>>(outp);
}

// round 10
// speedup vs baseline: 1.0586x; 1.0586x over previous
#include <cuda_runtime.h>
#include <cuda_bf16.h>
#include <stdint.h>
#include <math.h>

typedef unsigned int u32;

#define BATCH 2
#define C 192
#define HH 256
#define WW 256
#define HW (HH*WW)
#define NPIX (BATCH*HW)
#define NH 8
#define HD 24
#define WS 8
#define SS 4
#define HID 510
#define HID2 1020

// ---- scratch ----
__device__ float g_xt[NPIX*C];
__device__ float g_x2[NPIX*C];
__device__ __nv_bfloat16 g_xnb[(size_t)NPIX*C];
__device__ __nv_bfloat16 g_qkvb[(size_t)NPIX*576];
__device__ __nv_bfloat16 g_attnb[(size_t)NPIX*C];
__device__ __nv_bfloat16 g_ynb[(size_t)NPIX*C];
__device__ __nv_bfloat16 g_y[(size_t)NPIX*HID2];
__device__ __nv_bfloat16 g_gg[(size_t)NPIX*512];
__device__ __nv_bfloat16 g_qkvw[576*C];
__device__ __nv_bfloat16 g_projw[C*C];
__device__ __nv_bfloat16 g_pinb[HID2*C];
__device__ __nv_bfloat16 g_poutb[C*512];

__device__ __forceinline__ u32 sptr(const void* p) {
    return (u32)__cvta_generic_to_shared(p);
}
__device__ __forceinline__ void cpa16(u32 dst, const void* src, bool full) {
    int sz = full ? 16 : 0;
    asm volatile("cp.async.cg.shared.global [%0], [%1], 16, %2;" :: "r"(dst), "l"(src), "r"(sz));
}
__device__ __forceinline__ void ldsm4(u32& r0, u32& r1, u32& r2, u32& r3, u32 a) {
    asm volatile("ldmatrix.sync.aligned.m8n8.x4.shared.b16 {%0,%1,%2,%3}, [%4];"
        : "=r"(r0), "=r"(r1), "=r"(r2), "=r"(r3) : "r"(a));
}
__device__ __forceinline__ void ldsm2(u32& r0, u32& r1, u32 a) {
    asm volatile("ldmatrix.sync.aligned.m8n8.x2.shared.b16 {%0,%1}, [%2];"
        : "=r"(r0), "=r"(r1) : "r"(a));
}
__device__ __forceinline__ void ldsm4t(u32& r0, u32& r1, u32& r2, u32& r3, u32 a) {
    asm volatile("ldmatrix.sync.aligned.m8n8.x4.trans.shared.b16 {%0,%1,%2,%3}, [%4];"
        : "=r"(r0), "=r"(r1), "=r"(r2), "=r"(r3) : "r"(a));
}
__device__ __forceinline__ void mma_bf16(float& c0, float& c1, float& c2, float& c3,
    u32 a0, u32 a1, u32 a2, u32 a3, u32 b0, u32 b1) {
    asm volatile("mma.sync.aligned.m16n8k16.row.col.f32.bf16.bf16.f32 "
        "{%0,%1,%2,%3}, {%4,%5,%6,%7}, {%8,%9}, {%0,%1,%2,%3};"
        : "+f"(c0), "+f"(c1), "+f"(c2), "+f"(c3)
        : "r"(a0), "r"(a1), "r"(a2), "r"(a3), "r"(b0), "r"(b1));
}
__device__ __forceinline__ void mma_bf16_k8(float& c0, float& c1, float& c2, float& c3,
    u32 a0, u32 a1, u32 b0) {
    asm volatile("mma.sync.aligned.m16n8k8.row.col.f32.bf16.bf16.f32 "
        "{%0,%1,%2,%3}, {%4,%5}, {%6}, {%0,%1,%2,%3};"
        : "+f"(c0), "+f"(c1), "+f"(c2), "+f"(c3)
        : "r"(a0), "r"(a1), "r"(b0));
}
__device__ __forceinline__ u32 packbf(float a, float b) {
    __nv_bfloat162 t = __floats2bfloat162_rn(a, b);
    return *(u32*)&t;
}

// ================= merged weight convert ==================
__global__ void k_cvt_all(const float* __restrict__ qkvw, const float* __restrict__ projw,
                          const float* __restrict__ pinw, const float* __restrict__ poutw) {
    int i = blockIdx.x*256 + threadIdx.x;
    if (i < 576*C) {
        g_qkvw[i] = __float2bfloat16(qkvw[i]);
        return;
    }
    i -= 576*C;
    if (i < C*C) {
        g_projw[i] = __float2bfloat16(projw[i]);
        return;
    }
    i -= C*C;
    if (i < HID2*C) {
        g_pinb[i] = __float2bfloat16(pinw[i]);
        return;
    }
    i -= HID2*C;
    if (i < C*512) {
        int o = i >> 9;
        int k = i & 511;
        g_poutb[i] = __float2bfloat16(k < HID ? poutw[o*HID + k] : 0.f);
    }
}

// ================= K1: LN1 + transpose + window-permuted bf16 ==================
__global__ __launch_bounds__(256) void k_ln1(const float* __restrict__ x,
        const float* __restrict__ w, const float* __restrict__ b) {
    __shared__ float s[C*33];
    __shared__ float smu[32];
    __shared__ float srv[32];
    __shared__ int slot_s[32];
    int pix0 = blockIdx.x * 32;
    int bb = pix0 / HW;
    int hw0 = pix0 % HW;
    for (int e = threadIdx.x; e < C*32; e += 256) {
        int c = e >> 5;
        int p = e & 31;
        s[c*33 + p] = x[(size_t)(bb*C + c)*HW + hw0 + p];
    }
    __syncthreads();
    {
        int lane = threadIdx.x & 31;
        int warp = threadIdx.x >> 5;
        #pragma unroll
        for (int pp = 0; pp < 4; pp++) {
            int p = warp*4 + pp;
            float sum = 0.f;
            float sq = 0.f;
            #pragma unroll
            for (int i = 0; i < 6; i++) {
                float v = s[(lane + 32*i)*33 + p];
                sum += v;
                sq += v*v;
            }
            #pragma unroll
            for (int o = 16; o; o >>= 1) {
                sum += __shfl_xor_sync(0xffffffffu, sum, o);
                sq  += __shfl_xor_sync(0xffffffffu, sq, o);
            }
            if (lane == 0) {
                float mu = sum / C;
                smu[p] = mu;
                srv[p] = rsqrtf(sq / C - mu*mu + 1e-5f);
            }
        }
    }
    if (threadIdx.x < 32) {
        int p = threadIdx.x;
        int hw = hw0 + p;
        int r = hw >> 8;
        int cc = hw & 255;
        int sr = (r - SS + 256) & 255;
        int sc = (cc - SS + 256) & 255;
        slot_s[p] = (((bb << 10) + ((sr >> 3) << 5) + (sc >> 3)) << 6) + ((sr & 7) << 3) + (sc & 7);
    }
    __syncthreads();
    for (int e = threadIdx.x; e < C*32; e += 256) {
        int p = e / C;
        int c = e % C;
        float v = s[c*33 + p];
        g_xt[(pix0 + p)*C + c] = v;
        float ln = (v - smu[p]) * srv[p] * w[c] + b[c];
        g_xnb[(size_t)slot_s[p]*C + c] = __float2bfloat16(ln);
    }
}

// ================= tile loaders (R8 tiled GEMMs) ==================
__device__ __forceinline__ void qkv_load(__nv_bfloat16* Adst, __nv_bfloat16* Bdst,
                                         int pt, int ot, int k0, int tid) {
    #pragma unroll
    for (int i = 0; i < 2; i++) {
        int e = tid + i*256;
        int row = e >> 2;
        int seg = e & 3;
        cpa16(sptr(Adst + row*40 + seg*8), g_xnb + (size_t)(pt + row)*C + k0 + seg*8, true);
        int og = ot + row;
        bool ok = og < 576;
        cpa16(sptr(Bdst + row*40 + seg*8), g_qkvw + (size_t)(ok ? og : 0)*C + k0 + seg*8, ok);
    }
    asm volatile("cp.async.commit_group;" ::: "memory");
}

__device__ __forceinline__ void proj_load(__nv_bfloat16* Adst, __nv_bfloat16* Bdst,
                                          int pt, int ct, int k0, int tid) {
    #pragma unroll
    for (int i = 0; i < 2; i++) {
        int e = tid + i*256;
        int row = e >> 2;
        int seg = e & 3;
        cpa16(sptr(Adst + row*40 + seg*8), g_attnb + (size_t)(pt + row)*C + k0 + seg*8, true);
    }
    int row = tid >> 2;
    int seg = tid & 3;
    cpa16(sptr(Bdst + row*40 + seg*8), g_projw + (size_t)(ct + row)*C + k0 + seg*8, true);
    asm volatile("cp.async.commit_group;" ::: "memory");
}

__device__ __forceinline__ void pin_load(__nv_bfloat16* Adst, __nv_bfloat16* Bdst,
                                         int pt, int ot, int k0, int tid) {
    #pragma unroll
    for (int i = 0; i < 2; i++) {
        int e = tid + i*256;
        int row = e >> 2;
        int seg = e & 3;
        cpa16(sptr(Adst + row*40 + seg*8), g_ynb + (size_t)(pt + row)*C + k0 + seg*8, true);
        int og = ot + row;
        bool ok = og < HID2;
        cpa16(sptr(Bdst + row*40 + seg*8), g_pinb + (size_t)(ok ? og : 0)*C + k0 + seg*8, ok);
    }
    asm volatile("cp.async.commit_group;" ::: "memory");
}

__device__ __forceinline__ void pout_load(__nv_bfloat16* Adst, __nv_bfloat16* Bdst,
                                          int pt, int ct, int k0, int tid) {
    #pragma unroll
    for (int i = 0; i < 2; i++) {
        int e = tid + i*256;
        int row = e >> 2;
        int seg = e & 3;
        cpa16(sptr(Adst + row*40 + seg*8), g_gg + (size_t)(pt + row)*512 + k0 + seg*8, true);
    }
    int row = tid >> 2;
    int seg = tid & 3;
    cpa16(sptr(Bdst + row*40 + seg*8), g_poutb + (size_t)(ct + row)*512 + k0 + seg*8, true);
    asm volatile("cp.async.commit_group;" ::: "memory");
}

// ================= K2a: QKV GEMM bf16 (131072 x 576 x 192) -> bf16 ==================
__global__ __launch_bounds__(256,2) void k_qkv_b() {
    __shared__ __align__(16) __nv_bfloat16 As[2][5120];
    __shared__ __align__(16) __nv_bfloat16 Bs[2][5120];
    int pt = blockIdx.y*128;
    int ot = blockIdx.x*128;
    int tid = threadIdx.x;
    int lane = tid & 31;
    int warp = tid >> 5;
    int m0 = (warp >> 2)*64;
    int n0 = (warp & 3)*32;
    float acc[4][4][4] = {};

    qkv_load(As[0], Bs[0], pt, ot, 0, tid);

    for (int ch = 0; ch < 6; ch++) {
        asm volatile("cp.async.wait_group 0;" ::: "memory");
        __syncthreads();
        if (ch < 5) {
            qkv_load(As[(ch+1)&1], Bs[(ch+1)&1], pt, ot, (ch+1)*32, tid);
        }
        u32 ab = sptr(As[ch & 1]);
        u32 bbs = sptr(Bs[ch & 1]);
        #pragma unroll
        for (int ks = 0; ks < 2; ks++) {
            u32 av[4][4];
            u32 bv[4][2];
            #pragma unroll
            for (int mt = 0; mt < 4; mt++) {
                int row = m0 + mt*16 + (lane & 15);
                u32 ad = ab + (row*40 + ((lane >> 4) & 1)*8 + ks*16)*2;
                ldsm4(av[mt][0], av[mt][1], av[mt][2], av[mt][3], ad);
            }
            #pragma unroll
            for (int n2 = 0; n2 < 2; n2++) {
                int row = n0 + n2*16 + (lane & 7) + ((lane >> 4) & 1)*8;
                u32 ad = bbs + (row*40 + ((lane >> 3) & 1)*8 + ks*16)*2;
                u32 r0;
                u32 r1;
                u32 r2;
                u32 r3;
                ldsm4(r0, r1, r2, r3, ad);
                bv[n2*2+0][0] = r0;
                bv[n2*2+0][1] = r1;
                bv[n2*2+1][0] = r2;
                bv[n2*2+1][1] = r3;
            }
            #pragma unroll
            for (int mt = 0; mt < 4; mt++) {
                #pragma unroll
                for (int nt = 0; nt < 4; nt++) {
                    mma_bf16(acc[mt][nt][0], acc[mt][nt][1], acc[mt][nt][2], acc[mt][nt][3],
                             av[mt][0], av[mt][1], av[mt][2], av[mt][3], bv[nt][0], bv[nt][1]);
                }
            }
        }
    }

    const float qscale = 0.20412414523193154f;
    int lr = lane >> 2;
    int lc = lane & 3;
    #pragma unroll
    for (int mt = 0; mt < 4; mt++) {
        int row = pt + m0 + mt*16 + lr;
        #pragma unroll
        for (int nt = 0; nt < 4; nt++) {
            int col = ot + n0 + nt*8 + 2*lc;
            if (col < 576) {
                float s = (col < C) ? qscale : 1.f;
                __nv_bfloat162 v0;
                v0.x = __float2bfloat16(acc[mt][nt][0] * s);
                v0.y = __float2bfloat16(acc[mt][nt][1] * s);
                *(__nv_bfloat162*)&g_qkvb[(size_t)row*576 + col] = v0;
                __nv_bfloat162 v1;
                v1.x = __float2bfloat16(acc[mt][nt][2] * s);
                v1.y = __float2bfloat16(acc[mt][nt][3] * s);
                *(__nv_bfloat162*)&g_qkvb[(size_t)(row+8)*576 + col] = v1;
            }
        }
    }
}

// ================= K2b: tensor-core window attention (compact smem, 3 CTA/SM) ==================
// smem row: [Q 192 | K 192 | V 192 | pad 8], stride 584 bf16
#define SW 584
__global__ __launch_bounds__(128,3) void k_wattn_t(const float* __restrict__ rpb) {
    extern __shared__ __nv_bfloat16 smw[];
    __shared__ int lab[64];

    int tid = threadIdx.x;
    int lane = tid & 31;
    int warp = tid >> 5;
    int widx = blockIdx.x;
    int pix0 = widx * 64;
    int wy = (widx >> 5) & 31;
    int wx = widx & 31;

    if (tid < 64) {
        int i1 = tid >> 3;
        int j1 = tid & 7;
        int sr = wy*8 + i1;
        int sc = wx*8 + j1;
        lab[tid] = ((sr >= HH-WS) + (sr >= HH-SS))*3 + ((sc >= WW-WS) + (sc >= WW-SS));
    }
    // straight contiguous staging: 64 rows x 576 bf16
    for (int e = tid; e < 4608; e += 128) {
        int row = e / 72;
        int seg = e - row*72;
        cpa16(sptr(&smw[row*SW + seg*8]), g_qkvb + (size_t)(pix0 + row)*576 + seg*8, true);
    }
    asm volatile("cp.async.commit_group;" ::: "memory");
    asm volatile("cp.async.wait_group 0;" ::: "memory");
    __syncthreads();

    int lr = lane >> 2;
    int lc = lane & 3;
    int wrow0 = warp*16;
    int r0 = wrow0 + lr;
    int r1 = r0 + 8;
    int baseA = (((r0 >> 3) + 7)*15 + ((r0 & 7) - 2*lc + 7))*8;
    int baseB = (((r1 >> 3) + 7)*15 + ((r1 & 7) - 2*lc + 7))*8;
    int labA = lab[r0];
    int labB = lab[r1];
    u32 mbits = 0;
    #pragma unroll
    for (int f = 0; f < 8; f++) {
        int cA = f*8 + 2*lc;
        int lA = lab[cA];
        int lB = lab[cA + 1];
        if (labA != lA) { mbits |= 1u << (f*4 + 0); }
        if (labA != lB) { mbits |= 1u << (f*4 + 1); }
        if (labB != lA) { mbits |= 1u << (f*4 + 2); }
        if (labB != lB) { mbits |= 1u << (f*4 + 3); }
    }

    u32 smbase = sptr(smw);
    for (int h = 0; h < NH; h++) {
        int colQ = h*24;
        int colK = 192 + h*24;
        int colV = 384 + h*24;
        float c[8][4];
        #pragma unroll
        for (int f = 0; f < 8; f++) {
            c[f][0] = 0.f; c[f][1] = 0.f; c[f][2] = 0.f; c[f][3] = 0.f;
        }
        // ---- QK^T: K = 16 + 8 ----
        {
            u32 aq[4];
            u32 ad = smbase + ((wrow0 + (lane & 15))*SW + colQ + ((lane >> 4) & 1)*8)*2;
            ldsm4(aq[0], aq[1], aq[2], aq[3], ad);
            u32 a80;
            u32 a81;
            u32 ad8 = smbase + ((wrow0 + (lane & 15))*SW + colQ + 16)*2;
            ldsm2(a80, a81, ad8);
            u32 kb[8];
            {
                u32 t0; u32 t1; u32 t2; u32 t3;
                u32 kd0 = smbase + (lane*SW + colK + 16)*2;
                ldsm4(t0, t1, t2, t3, kd0);
                kb[0] = t0; kb[1] = t1; kb[2] = t2; kb[3] = t3;
                u32 kd1 = smbase + ((32 + lane)*SW + colK + 16)*2;
                ldsm4(t0, t1, t2, t3, kd1);
                kb[4] = t0; kb[5] = t1; kb[6] = t2; kb[7] = t3;
            }
            #pragma unroll
            for (int n2 = 0; n2 < 4; n2++) {
                u32 b0;
                u32 b1;
                u32 b2;
                u32 b3;
                u32 bd = smbase + ((n2*16 + (lane & 7) + ((lane >> 4) & 1)*8)*SW
                                   + colK + ((lane >> 3) & 1)*8)*2;
                ldsm4(b0, b1, b2, b3, bd);
                mma_bf16(c[2*n2][0], c[2*n2][1], c[2*n2][2], c[2*n2][3],
                         aq[0], aq[1], aq[2], aq[3], b0, b1);
                mma_bf16(c[2*n2+1][0], c[2*n2+1][1], c[2*n2+1][2], c[2*n2+1][3],
                         aq[0], aq[1], aq[2], aq[3], b2, b3);
                mma_bf16_k8(c[2*n2][0], c[2*n2][1], c[2*n2][2], c[2*n2][3],
                            a80, a81, kb[2*n2]);
                mma_bf16_k8(c[2*n2+1][0], c[2*n2+1][1], c[2*n2+1][2], c[2*n2+1][3],
                            a80, a81, kb[2*n2+1]);
            }
        }
        // ---- bias + mask ----
        int hA = baseA + h;
        int hB = baseB + h;
        #pragma unroll
        for (int f = 0; f < 8; f++) {
            c[f][0] += __ldg(&rpb[hA - 120*f])     + (((mbits >> (f*4+0)) & 1) ? -100.f : 0.f);
            c[f][1] += __ldg(&rpb[hA - 120*f - 8]) + (((mbits >> (f*4+1)) & 1) ? -100.f : 0.f);
            c[f][2] += __ldg(&rpb[hB - 120*f])     + (((mbits >> (f*4+2)) & 1) ? -100.f : 0.f);
            c[f][3] += __ldg(&rpb[hB - 120*f - 8]) + (((mbits >> (f*4+3)) & 1) ? -100.f : 0.f);
        }
        // ---- softmax ----
        float mx0 = -1e30f;
        float mx1 = -1e30f;
        #pragma unroll
        for (int f = 0; f < 8; f++) {
            mx0 = fmaxf(mx0, fmaxf(c[f][0], c[f][1]));
            mx1 = fmaxf(mx1, fmaxf(c[f][2], c[f][3]));
        }
        mx0 = fmaxf(mx0, __shfl_xor_sync(0xffffffffu, mx0, 1));
        mx0 = fmaxf(mx0, __shfl_xor_sync(0xffffffffu, mx0, 2));
        mx1 = fmaxf(mx1, __shfl_xor_sync(0xffffffffu, mx1, 1));
        mx1 = fmaxf(mx1, __shfl_xor_sync(0xffffffffu, mx1, 2));
        float s0 = 0.f;
        float s1 = 0.f;
        #pragma unroll
        for (int f = 0; f < 8; f++) {
            c[f][0] = __expf(c[f][0] - mx0);
            c[f][1] = __expf(c[f][1] - mx0);
            c[f][2] = __expf(c[f][2] - mx1);
            c[f][3] = __expf(c[f][3] - mx1);
            s0 += c[f][0] + c[f][1];
            s1 += c[f][2] + c[f][3];
        }
        s0 += __shfl_xor_sync(0xffffffffu, s0, 1);
        s0 += __shfl_xor_sync(0xffffffffu, s0, 2);
        s1 += __shfl_xor_sync(0xffffffffu, s1, 1);
        s1 += __shfl_xor_sync(0xffffffffu, s1, 2);
        float inv0 = 1.f / s0;
        float inv1 = 1.f / s1;
        u32 ap[4][4];
        #pragma unroll
        for (int j = 0; j < 4; j++) {
            ap[j][0] = packbf(c[2*j][0]*inv0,   c[2*j][1]*inv0);
            ap[j][1] = packbf(c[2*j][2]*inv1,   c[2*j][3]*inv1);
            ap[j][2] = packbf(c[2*j+1][0]*inv0, c[2*j+1][1]*inv0);
            ap[j][3] = packbf(c[2*j+1][2]*inv1, c[2*j+1][3]*inv1);
        }
        // ---- AV ----
        float o[3][4];
        #pragma unroll
        for (int nt = 0; nt < 3; nt++) {
            o[nt][0] = 0.f; o[nt][1] = 0.f; o[nt][2] = 0.f; o[nt][3] = 0.f;
        }
        #pragma unroll
        for (int j = 0; j < 4; j++) {
            u32 lo0; u32 lo1; u32 lo2; u32 lo3;
            u32 hi0; u32 hi1; u32 hi2; u32 hi3;
            u32 vlo = smbase + ((j*16 + (lane & 7))*SW + colV + (lane >> 3)*8)*2;
            u32 vhi = smbase + ((j*16 + 8 + (lane & 7))*SW + colV + (lane >> 3)*8)*2;
            ldsm4t(lo0, lo1, lo2, lo3, vlo);
            ldsm4t(hi0, hi1, hi2, hi3, vhi);
            mma_bf16(o[0][0], o[0][1], o[0][2], o[0][3], ap[j][0], ap[j][1], ap[j][2], ap[j][3], lo0, hi0);
            mma_bf16(o[1][0], o[1][1], o[1][2], o[1][3], ap[j][0], ap[j][1], ap[j][2], ap[j][3], lo1, hi1);
            mma_bf16(o[2][0], o[2][1], o[2][2], o[2][3], ap[j][0], ap[j][1], ap[j][2], ap[j][3], lo2, hi2);
        }
        #pragma unroll
        for (int nt = 0; nt < 3; nt++) {
            int col = h*24 + nt*8 + 2*lc;
            __nv_bfloat162 v0;
            v0.x = __float2bfloat16(o[nt][0]);
            v0.y = __float2bfloat16(o[nt][1]);
            *(__nv_bfloat162*)&g_attnb[(size_t)(pix0 + r0)*C + col] = v0;
            __nv_bfloat162 v1;
            v1.x = __float2bfloat16(o[nt][2]);
            v1.y = __float2bfloat16(o[nt][3]);
            *(__nv_bfloat162*)&g_attnb[(size_t)(pix0 + r1)*C + col] = v1;
        }
    }
}

// ================= K2c: proj GEMM bf16 + bias + residual ==================
__global__ __launch_bounds__(256,2) void k_proj_b(const float* __restrict__ pb) {
    __shared__ __align__(16) __nv_bfloat16 As[2][5120];
    __shared__ __align__(16) __nv_bfloat16 Bs[2][2560];
    int pt = blockIdx.y*128;
    int ct = blockIdx.x*64;
    int tid = threadIdx.x;
    int lane = tid & 31;
    int warp = tid >> 5;
    int m0 = (warp & 3)*32;
    int n0 = (warp >> 2)*32;
    float acc[2][4][4] = {};

    proj_load(As[0], Bs[0], pt, ct, 0, tid);

    for (int ch = 0; ch < 6; ch++) {
        asm volatile("cp.async.wait_group 0;" ::: "memory");
        __syncthreads();
        if (ch < 5) {
            proj_load(As[(ch+1)&1], Bs[(ch+1)&1], pt, ct, (ch+1)*32, tid);
        }
        u32 ab = sptr(As[ch & 1]);
        u32 bbs = sptr(Bs[ch & 1]);
        #pragma unroll
        for (int ks = 0; ks < 2; ks++) {
            u32 av[2][4];
            u32 bv[4][2];
            #pragma unroll
            for (int mt = 0; mt < 2; mt++) {
                int row = m0 + mt*16 + (lane & 15);
                u32 ad = ab + (row*40 + ((lane >> 4) & 1)*8 + ks*16)*2;
                ldsm4(av[mt][0], av[mt][1], av[mt][2], av[mt][3], ad);
            }
            #pragma unroll
            for (int n2 = 0; n2 < 2; n2++) {
                int row = n0 + n2*16 + (lane & 7) + ((lane >> 4) & 1)*8;
                u32 ad = bbs + (row*40 + ((lane >> 3) & 1)*8 + ks*16)*2;
                u32 r0;
                u32 r1;
                u32 r2;
                u32 r3;
                ldsm4(r0, r1, r2, r3, ad);
                bv[n2*2+0][0] = r0;
                bv[n2*2+0][1] = r1;
                bv[n2*2+1][0] = r2;
                bv[n2*2+1][1] = r3;
            }
            #pragma unroll
            for (int mt = 0; mt < 2; mt++) {
                #pragma unroll
                for (int nt = 0; nt < 4; nt++) {
                    mma_bf16(acc[mt][nt][0], acc[mt][nt][1], acc[mt][nt][2], acc[mt][nt][3],
                             av[mt][0], av[mt][1], av[mt][2], av[mt][3], bv[nt][0], bv[nt][1]);
                }
            }
        }
    }

    int lr = lane >> 2;
    int lc = lane & 3;
    #pragma unroll
    for (int mt = 0; mt < 2; mt++) {
        #pragma unroll
        for (int half = 0; half < 2; half++) {
            int row = pt + m0 + mt*16 + lr + half*8;
            int bb = row >> 16;
            int widx = (row >> 6) & 1023;
            int tok = row & 63;
            int r = (((widx >> 5) << 3) + (tok >> 3) + SS) & 255;
            int c2 = (((widx & 31) << 3) + (tok & 7) + SS) & 255;
            int gbase = ((bb*HH + r)*WW + c2)*C;
            #pragma unroll
            for (int nt = 0; nt < 4; nt++) {
                int col = ct + n0 + nt*8 + 2*lc;
                float2 v;
                v.x = acc[mt][nt][half*2+0] + pb[col] + g_xt[gbase + col];
                v.y = acc[mt][nt][half*2+1] + pb[col+1] + g_xt[gbase + col + 1];
                *(float2*)&g_x2[gbase + col] = v;
            }
        }
    }
}

// ================= K3: LN2 -> bf16 ==================
__global__ __launch_bounds__(256) void k_ln2(const float* __restrict__ w,
                                             const float* __restrict__ b) {
    int pix = blockIdx.x*8 + (threadIdx.x >> 5);
    int lane = threadIdx.x & 31;
    const float* row = g_x2 + (size_t)pix*C;
    float v[6];
    float sum = 0.f;
    float sq = 0.f;
    #pragma unroll
    for (int i = 0; i < 6; i++) {
        v[i] = row[lane + 32*i];
        sum += v[i];
        sq += v[i]*v[i];
    }
    #pragma unroll
    for (int o = 16; o; o >>= 1) {
        sum += __shfl_xor_sync(0xffffffffu, sum, o);
        sq  += __shfl_xor_sync(0xffffffffu, sq, o);
    }
    float mu = sum / C;
    float rv = rsqrtf(sq / C - mu*mu + 1e-5f);
    __nv_bfloat16* outp = g_ynb + (size_t)pix*C;
    #pragma unroll
    for (int i = 0; i < 6; i++) {
        int c = lane + 32*i;
        outp[c] = __float2bfloat16((v[i]-mu)*rv*w[c] + b[c]);
    }
}

// ================= K4: pin GEMM bf16 (131072 x 1020 x 192) ==================
__global__ __launch_bounds__(256,2) void k_pin_b() {
    __shared__ __align__(16) __nv_bfloat16 As[2][5120];
    __shared__ __align__(16) __nv_bfloat16 Bs[2][5120];
    int pt = blockIdx.y*128;
    int ot = blockIdx.x*128;
    int tid = threadIdx.x;
    int lane = tid & 31;
    int warp = tid >> 5;
    int m0 = (warp >> 2)*64;
    int n0 = (warp & 3)*32;
    float acc[4][4][4] = {};

    pin_load(As[0], Bs[0], pt, ot, 0, tid);

    for (int ch = 0; ch < 6; ch++) {
        asm volatile("cp.async.wait_group 0;" ::: "memory");
        __syncthreads();
        if (ch < 5) {
            pin_load(As[(ch+1)&1], Bs[(ch+1)&1], pt, ot, (ch+1)*32, tid);
        }
        u32 ab = sptr(As[ch & 1]);
        u32 bbs = sptr(Bs[ch & 1]);
        #pragma unroll
        for (int ks = 0; ks < 2; ks++) {
            u32 av[4][4];
            u32 bv[4][2];
            #pragma unroll
            for (int mt = 0; mt < 4; mt++) {
                int row = m0 + mt*16 + (lane & 15);
                u32 ad = ab + (row*40 + ((lane >> 4) & 1)*8 + ks*16)*2;
                ldsm4(av[mt][0], av[mt][1], av[mt][2], av[mt][3], ad);
            }
            #pragma unroll
            for (int n2 = 0; n2 < 2; n2++) {
                int row = n0 + n2*16 + (lane & 7) + ((lane >> 4) & 1)*8;
                u32 ad = bbs + (row*40 + ((lane >> 3) & 1)*8 + ks*16)*2;
                u32 r0;
                u32 r1;
                u32 r2;
                u32 r3;
                ldsm4(r0, r1, r2, r3, ad);
                bv[n2*2+0][0] = r0;
                bv[n2*2+0][1] = r1;
                bv[n2*2+1][0] = r2;
                bv[n2*2+1][1] = r3;
            }
            #pragma unroll
            for (int mt = 0; mt < 4; mt++) {
                #pragma unroll
                for (int nt = 0; nt < 4; nt++) {
                    mma_bf16(acc[mt][nt][0], acc[mt][nt][1], acc[mt][nt][2], acc[mt][nt][3],
                             av[mt][0], av[mt][1], av[mt][2], av[mt][3], bv[nt][0], bv[nt][1]);
                }
            }
        }
    }

    int lr = lane >> 2;
    int lc = lane & 3;
    #pragma unroll
    for (int mt = 0; mt < 4; mt++) {
        int row = pt + m0 + mt*16 + lr;
        #pragma unroll
        for (int nt = 0; nt < 4; nt++) {
            int col = ot + n0 + nt*8 + 2*lc;
            if (col < HID2) {
                __nv_bfloat162 v0;
                v0.x = __float2bfloat16(acc[mt][nt][0]);
                v0.y = __float2bfloat16(acc[mt][nt][1]);
                *(__nv_bfloat162*)&g_y[(size_t)row*HID2 + col] = v0;
                __nv_bfloat162 v1;
                v1.x = __float2bfloat16(acc[mt][nt][2]);
                v1.y = __float2bfloat16(acc[mt][nt][3]);
                *(__nv_bfloat162*)&g_y[(size_t)(row+8)*HID2 + col] = v1;
            }
        }
    }
}

// ================= K5: depthwise 3x3 + gated GELU (bf162-vectorized) ==================
__global__ __launch_bounds__(256) void k_dw2(const float* __restrict__ dw) {
    int bx = blockIdx.x;
    int t = threadIdx.x;
    int xseg = (bx & 63) * 4;
    int r = (bx >> 6) & 255;
    int bb = bx >> 14;
    size_t prow = (size_t)(bb*HH + r)*WW;
    if (t >= 255) {
        if (t == 255) {
            #pragma unroll
            for (int o = 0; o < 4; o++) {
                *(u32*)&g_gg[(prow + xseg + o)*512 + 510] = 0u;
            }
        }
        return;
    }
    int c = t*2;
    float a0[3][6];
    float a1[3][6];
    float b0[3][6];
    float b1[3][6];
    #pragma unroll
    for (int dy = 0; dy < 3; dy++) {
        int rowi = r + dy - 1;
        bool rok = (unsigned)rowi < 256u;
        #pragma unroll
        for (int dx = 0; dx < 6; dx++) {
            int col = xseg + dx - 1;
            bool ok = rok && ((unsigned)col < 256u);
            float2 va = make_float2(0.f, 0.f);
            float2 vb = make_float2(0.f, 0.f);
            if (ok) {
                size_t base = ((size_t)(bb*HH + rowi)*WW + col)*HID2;
                va = __bfloat1622float2(*(const __nv_bfloat162*)&g_y[base + c]);
                vb = __bfloat1622float2(*(const __nv_bfloat162*)&g_y[base + c + HID]);
            }
            a0[dy][dx] = va.x;
            a1[dy][dx] = va.y;
            b0[dy][dx] = vb.x;
            b1[dy][dx] = vb.y;
        }
    }
    float wa0[9];
    float wa1[9];
    float wb0[9];
    float wb1[9];
    #pragma unroll
    for (int q = 0; q < 9; q++) {
        wa0[q] = dw[c*9 + q];
        wa1[q] = dw[(c+1)*9 + q];
        wb0[q] = dw[(c+HID)*9 + q];
        wb1[q] = dw[(c+HID+1)*9 + q];
    }
    #pragma unroll
    for (int o = 0; o < 4; o++) {
        float s0 = 0.f;
        float s1 = 0.f;
        float g0 = 0.f;
        float g1 = 0.f;
        #pragma unroll
        for (int ky = 0; ky < 3; ky++) {
            #pragma unroll
            for (int kx = 0; kx < 3; kx++) {
                int q = ky*3 + kx;
                s0 += wa0[q]*a0[ky][o+kx];
                s1 += wa1[q]*a1[ky][o+kx];
                g0 += wb0[q]*b0[ky][o+kx];
                g1 += wb1[q]*b1[ky][o+kx];
            }
        }
        float e0 = 0.5f*s0*(1.f + erff(s0*0.70710678118654752f)) * g0;
        float e1 = 0.5f*s1*(1.f + erff(s1*0.70710678118654752f)) * g1;
        *(__nv_bfloat162*)&g_gg[(prow + xseg + o)*512 + c] = __floats2bfloat162_rn(e0, e1);
    }
}

// ================= K6: pout GEMM bf16 + residual -> NCHW ==================
#define SPP 132
__global__ __launch_bounds__(256,2) void k_pout_b(float* __restrict__ outp) {
    __shared__ __align__(16) float smem_f[8448];
    __nv_bfloat16* As = (__nv_bfloat16*)smem_f;
    __nv_bfloat16* Bs = (__nv_bfloat16*)(smem_f + 5120);
    float* Cs = smem_f;
    int pt = blockIdx.y*128;
    int ct = blockIdx.x*64;
    int tid = threadIdx.x;
    int lane = tid & 31;
    int warp = tid >> 5;
    int m0 = (warp & 3)*32;
    int n0 = (warp >> 2)*32;
    float acc[2][4][4] = {};

    pout_load(As, Bs, pt, ct, 0, tid);

    for (int ch = 0; ch < 16; ch++) {
        asm volatile("cp.async.wait_group 0;" ::: "memory");
        __syncthreads();
        if (ch < 15) {
            int st = (ch+1) & 1;
            pout_load(As + st*5120, Bs + st*2560, pt, ct, (ch+1)*32, tid);
        }
        u32 ab = sptr(As + (ch & 1)*5120);
        u32 bbs = sptr(Bs + (ch & 1)*2560);
        #pragma unroll
        for (int ks = 0; ks < 2; ks++) {
            u32 av[2][4];
            u32 bv[4][2];
            #pragma unroll
            for (int mt = 0; mt < 2; mt++) {
                int row = m0 + mt*16 + (lane & 15);
                u32 ad = ab + (row*40 + ((lane >> 4) & 1)*8 + ks*16)*2;
                ldsm4(av[mt][0], av[mt][1], av[mt][2], av[mt][3], ad);
            }
            #pragma unroll
            for (int n2 = 0; n2 < 2; n2++) {
                int row = n0 + n2*16 + (lane & 7) + ((lane >> 4) & 1)*8;
                u32 ad = bbs + (row*40 + ((lane >> 3) & 1)*8 + ks*16)*2;
                u32 r0;
                u32 r1;
                u32 r2;
                u32 r3;
                ldsm4(r0, r1, r2, r3, ad);
                bv[n2*2+0][0] = r0;
                bv[n2*2+0][1] = r1;
                bv[n2*2+1][0] = r2;
                bv[n2*2+1][1] = r3;
            }
            #pragma unroll
            for (int mt = 0; mt < 2; mt++) {
                #pragma unroll
                for (int nt = 0; nt < 4; nt++) {
                    mma_bf16(acc[mt][nt][0], acc[mt][nt][1], acc[mt][nt][2], acc[mt][nt][3],
                             av[mt][0], av[mt][1], av[mt][2], av[mt][3], bv[nt][0], bv[nt][1]);
                }
            }
        }
    }
    __syncthreads();

    int lr = lane >> 2;
    int lc = lane & 3;
    #pragma unroll
    for (int mt = 0; mt < 2; mt++) {
        int row = m0 + mt*16 + lr;
        #pragma unroll
        for (int nt = 0; nt < 4; nt++) {
            int col = n0 + nt*8 + 2*lc;
            Cs[col*SPP + row] = acc[mt][nt][0];
            Cs[(col+1)*SPP + row] = acc[mt][nt][1];
            Cs[col*SPP + row + 8] = acc[mt][nt][2];
            Cs[(col+1)*SPP + row + 8] = acc[mt][nt][3];
        }
    }
    __syncthreads();
    for (int e = tid; e < 2048; e += 256) {
        int p = e >> 4;
        int c4 = e & 15;
        float4 v = *(const float4*)&g_x2[(size_t)(pt + p)*C + ct + c4*4];
        Cs[(c4*4+0)*SPP + p] += v.x;
        Cs[(c4*4+1)*SPP + p] += v.y;
        Cs[(c4*4+2)*SPP + p] += v.z;
        Cs[(c4*4+3)*SPP + p] += v.w;
    }
    __syncthreads();
    int bb = pt >> 16;
    int hw0 = pt & 65535;
    for (int e = tid; e < 2048; e += 256) {
        int c = e >> 5;
        int p4 = e & 31;
        float4 v = *(const float4*)&Cs[c*SPP + p4*4];
        *(float4*)&outp[((size_t)(bb*C + ct + c))*HW + hw0 + p4*4] = v;
    }
}

// ================= launch ==================
extern "C" void kernel_launch(void* const* d_in, const int* in_sizes, int n_in,
                              void* d_out, int out_size) {
    const float* x      = (const float*)d_in[0];
    const float* n1w    = (const float*)d_in[1];
    const float* n1b    = (const float*)d_in[2];
    const float* qkv_w  = (const float*)d_in[3];
    const float* rpb    = (const float*)d_in[4];
    const float* proj_w = (const float*)d_in[5];
    const float* proj_b = (const float*)d_in[6];
    const float* n2w    = (const float*)d_in[7];
    const float* n2b    = (const float*)d_in[8];
    const float* pin_w  = (const float*)d_in[9];
    const float* dw_w   = (const float*)d_in[10];
    const float* pout_w = (const float*)d_in[11];
    float* outp = (float*)d_out;

    const int wattn_smem = 64*SW*2;   // 74752
    cudaFuncSetAttribute(k_wattn_t, cudaFuncAttributeMaxDynamicSharedMemorySize, wattn_smem);

    const int cvt_total = 576*C + C*C + HID2*C + C*512;
    k_cvt_all<<<(cvt_total + 255)/256, 256>>>(qkv_w, proj_w, pin_w, pout_w);
    k_ln1    <<<NPIX/32, 256>>>(x, n1w, n1b);
    k_qkv_b  <<<dim3(5, NPIX/128), 256>>>();
    k_wattn_t<<<2048, 128, wattn_smem>>>(rpb);
    k_proj_b <<<dim3(3, NPIX/128), 256>>>(proj_b);
    k_ln2    <<<NPIX/8, 256>>>(n2w, n2b);
    k_pin_b  <<<dim3(8, NPIX/128), 256>>>();
    k_dw2    <<<BATCH*HH*(WW/4), 256>>>(dw_w);
    k_pout_b <<<dim3(3, NPIX/128), 256>>>(outp);
}

// round 11
// speedup vs baseline: 1.0600x; 1.0013x over previous
#include <cuda_runtime.h>
#include <cuda_bf16.h>
#include <stdint.h>
#include <math.h>

typedef unsigned int u32;
typedef unsigned long long u64;

#define BATCH 2
#define C 192
#define HH 256
#define WW 256
#define HW (HH*WW)
#define NPIX (BATCH*HW)
#define NH 8
#define HD 24
#define WS 8
#define SS 4
#define HID 510
#define HID2 1020

// ---- scratch ----
__device__ float g_xt[NPIX*C];
__device__ float g_x2[NPIX*C];
__device__ __nv_bfloat16 g_xnb[(size_t)NPIX*C];
__device__ __nv_bfloat16 g_qkvb[(size_t)NPIX*576];
__device__ __nv_bfloat16 g_attnb[(size_t)NPIX*C];
__device__ __nv_bfloat16 g_ynb[(size_t)NPIX*C];
__device__ __nv_bfloat16 g_y[(size_t)NPIX*HID2];
__device__ __nv_bfloat16 g_gg[(size_t)NPIX*512];
__device__ __nv_bfloat16 g_qkvw[576*C];
__device__ __nv_bfloat16 g_projw[C*C];
__device__ __nv_bfloat16 g_pinb[HID2*C];
__device__ __nv_bfloat16 g_poutb[C*512];

__device__ __forceinline__ u32 sptr(const void* p) {
    return (u32)__cvta_generic_to_shared(p);
}
__device__ __forceinline__ void cpa16(u32 dst, const void* src, bool full) {
    int sz = full ? 16 : 0;
    asm volatile("cp.async.cg.shared.global [%0], [%1], 16, %2;" :: "r"(dst), "l"(src), "r"(sz));
}
__device__ __forceinline__ void ldsm4(u32& r0, u32& r1, u32& r2, u32& r3, u32 a) {
    asm volatile("ldmatrix.sync.aligned.m8n8.x4.shared.b16 {%0,%1,%2,%3}, [%4];"
        : "=r"(r0), "=r"(r1), "=r"(r2), "=r"(r3) : "r"(a));
}
__device__ __forceinline__ void ldsm2(u32& r0, u32& r1, u32 a) {
    asm volatile("ldmatrix.sync.aligned.m8n8.x2.shared.b16 {%0,%1}, [%2];"
        : "=r"(r0), "=r"(r1) : "r"(a));
}
__device__ __forceinline__ void ldsm4t(u32& r0, u32& r1, u32& r2, u32& r3, u32 a) {
    asm volatile("ldmatrix.sync.aligned.m8n8.x4.trans.shared.b16 {%0,%1,%2,%3}, [%4];"
        : "=r"(r0), "=r"(r1), "=r"(r2), "=r"(r3) : "r"(a));
}
__device__ __forceinline__ void mma_bf16(float& c0, float& c1, float& c2, float& c3,
    u32 a0, u32 a1, u32 a2, u32 a3, u32 b0, u32 b1) {
    asm volatile("mma.sync.aligned.m16n8k16.row.col.f32.bf16.bf16.f32 "
        "{%0,%1,%2,%3}, {%4,%5,%6,%7}, {%8,%9}, {%0,%1,%2,%3};"
        : "+f"(c0), "+f"(c1), "+f"(c2), "+f"(c3)
        : "r"(a0), "r"(a1), "r"(a2), "r"(a3), "r"(b0), "r"(b1));
}
__device__ __forceinline__ void mma_bf16_k8(float& c0, float& c1, float& c2, float& c3,
    u32 a0, u32 a1, u32 b0) {
    asm volatile("mma.sync.aligned.m16n8k8.row.col.f32.bf16.bf16.f32 "
        "{%0,%1,%2,%3}, {%4,%5}, {%6}, {%0,%1,%2,%3};"
        : "+f"(c0), "+f"(c1), "+f"(c2), "+f"(c3)
        : "r"(a0), "r"(a1), "r"(b0));
}
__device__ __forceinline__ u32 packbf(float a, float b) {
    __nv_bfloat162 t = __floats2bfloat162_rn(a, b);
    return *(u32*)&t;
}
// ---- packed f32x2 helpers ----
__device__ __forceinline__ u64 pk2(float x, float y) {
    u64 r;
    asm("mov.b64 %0, {%1,%2};" : "=l"(r) : "f"(x), "f"(y));
    return r;
}
__device__ __forceinline__ void upk2(float& x, float& y, u64 v) {
    asm("mov.b64 {%0,%1}, %2;" : "=f"(x), "=f"(y) : "l"(v));
}
__device__ __forceinline__ u64 fma2(u64 a, u64 b, u64 c) {
    u64 d;
    asm("fma.rn.f32x2 %0, %1, %2, %3;" : "=l"(d) : "l"(a), "l"(b), "l"(c));
    return d;
}

// ================= merged weight convert ==================
__global__ void k_cvt_all(const float* __restrict__ qkvw, const float* __restrict__ projw,
                          const float* __restrict__ pinw, const float* __restrict__ poutw) {
    int i = blockIdx.x*256 + threadIdx.x;
    if (i < 576*C) {
        g_qkvw[i] = __float2bfloat16(qkvw[i]);
        return;
    }
    i -= 576*C;
    if (i < C*C) {
        g_projw[i] = __float2bfloat16(projw[i]);
        return;
    }
    i -= C*C;
    if (i < HID2*C) {
        g_pinb[i] = __float2bfloat16(pinw[i]);
        return;
    }
    i -= HID2*C;
    if (i < C*512) {
        int o = i >> 9;
        int k = i & 511;
        g_poutb[i] = __float2bfloat16(k < HID ? poutw[o*HID + k] : 0.f);
    }
}

// ================= K1: LN1 + transpose + window-permuted bf16 ==================
__global__ __launch_bounds__(256) void k_ln1(const float* __restrict__ x,
        const float* __restrict__ w, const float* __restrict__ b) {
    __shared__ float s[C*33];
    __shared__ float smu[32];
    __shared__ float srv[32];
    __shared__ int slot_s[32];
    int pix0 = blockIdx.x * 32;
    int bb = pix0 / HW;
    int hw0 = pix0 % HW;
    for (int e = threadIdx.x; e < C*32; e += 256) {
        int c = e >> 5;
        int p = e & 31;
        s[c*33 + p] = x[(size_t)(bb*C + c)*HW + hw0 + p];
    }
    __syncthreads();
    {
        int lane = threadIdx.x & 31;
        int warp = threadIdx.x >> 5;
        #pragma unroll
        for (int pp = 0; pp < 4; pp++) {
            int p = warp*4 + pp;
            float sum = 0.f;
            float sq = 0.f;
            #pragma unroll
            for (int i = 0; i < 6; i++) {
                float v = s[(lane + 32*i)*33 + p];
                sum += v;
                sq += v*v;
            }
            #pragma unroll
            for (int o = 16; o; o >>= 1) {
                sum += __shfl_xor_sync(0xffffffffu, sum, o);
                sq  += __shfl_xor_sync(0xffffffffu, sq, o);
            }
            if (lane == 0) {
                float mu = sum / C;
                smu[p] = mu;
                srv[p] = rsqrtf(sq / C - mu*mu + 1e-5f);
            }
        }
    }
    if (threadIdx.x < 32) {
        int p = threadIdx.x;
        int hw = hw0 + p;
        int r = hw >> 8;
        int cc = hw & 255;
        int sr = (r - SS + 256) & 255;
        int sc = (cc - SS + 256) & 255;
        slot_s[p] = (((bb << 10) + ((sr >> 3) << 5) + (sc >> 3)) << 6) + ((sr & 7) << 3) + (sc & 7);
    }
    __syncthreads();
    for (int e = threadIdx.x; e < C*32; e += 256) {
        int p = e / C;
        int c = e % C;
        float v = s[c*33 + p];
        g_xt[(pix0 + p)*C + c] = v;
        float ln = (v - smu[p]) * srv[p] * w[c] + b[c];
        g_xnb[(size_t)slot_s[p]*C + c] = __float2bfloat16(ln);
    }
}

// ================= tile loaders ==================
__device__ __forceinline__ void qkv_load(__nv_bfloat16* Adst, __nv_bfloat16* Bdst,
                                         int pt, int ot, int k0, int tid) {
    #pragma unroll
    for (int i = 0; i < 2; i++) {
        int e = tid + i*256;
        int row = e >> 2;
        int seg = e & 3;
        cpa16(sptr(Adst + row*40 + seg*8), g_xnb + (size_t)(pt + row)*C + k0 + seg*8, true);
        int og = ot + row;
        bool ok = og < 576;
        cpa16(sptr(Bdst + row*40 + seg*8), g_qkvw + (size_t)(ok ? og : 0)*C + k0 + seg*8, ok);
    }
    asm volatile("cp.async.commit_group;" ::: "memory");
}

__device__ __forceinline__ void proj_load(__nv_bfloat16* Adst, __nv_bfloat16* Bdst,
                                          int pt, int ct, int k0, int tid) {
    #pragma unroll
    for (int i = 0; i < 2; i++) {
        int e = tid + i*256;
        int row = e >> 2;
        int seg = e & 3;
        cpa16(sptr(Adst + row*40 + seg*8), g_attnb + (size_t)(pt + row)*C + k0 + seg*8, true);
    }
    int row = tid >> 2;
    int seg = tid & 3;
    cpa16(sptr(Bdst + row*40 + seg*8), g_projw + (size_t)(ct + row)*C + k0 + seg*8, true);
    asm volatile("cp.async.commit_group;" ::: "memory");
}

__device__ __forceinline__ void pin_load(__nv_bfloat16* Adst, __nv_bfloat16* Bdst,
                                         int pt, int ot, int k0, int tid) {
    #pragma unroll
    for (int i = 0; i < 2; i++) {
        int e = tid + i*256;
        int row = e >> 2;
        int seg = e & 3;
        cpa16(sptr(Adst + row*40 + seg*8), g_ynb + (size_t)(pt + row)*C + k0 + seg*8, true);
        int og = ot + row;
        bool ok = og < HID2;
        cpa16(sptr(Bdst + row*40 + seg*8), g_pinb + (size_t)(ok ? og : 0)*C + k0 + seg*8, ok);
    }
    asm volatile("cp.async.commit_group;" ::: "memory");
}

__device__ __forceinline__ void pout_load(__nv_bfloat16* Adst, __nv_bfloat16* Bdst,
                                          int pt, int ct, int k0, int tid) {
    #pragma unroll
    for (int i = 0; i < 2; i++) {
        int e = tid + i*256;
        int row = e >> 2;
        int seg = e & 3;
        cpa16(sptr(Adst + row*40 + seg*8), g_gg + (size_t)(pt + row)*512 + k0 + seg*8, true);
    }
    int row = tid >> 2;
    int seg = tid & 3;
    cpa16(sptr(Bdst + row*40 + seg*8), g_poutb + (size_t)(ct + row)*512 + k0 + seg*8, true);
    asm volatile("cp.async.commit_group;" ::: "memory");
}

// ================= K2a: QKV GEMM bf16 (131072 x 576 x 192) -> bf16 ==================
__global__ __launch_bounds__(256,2) void k_qkv_b() {
    __shared__ __align__(16) __nv_bfloat16 As[2][5120];
    __shared__ __align__(16) __nv_bfloat16 Bs[2][5120];
    int pt = blockIdx.y*128;
    int ot = blockIdx.x*128;
    int tid = threadIdx.x;
    int lane = tid & 31;
    int warp = tid >> 5;
    int m0 = (warp >> 2)*64;
    int n0 = (warp & 3)*32;
    float acc[4][4][4] = {};

    qkv_load(As[0], Bs[0], pt, ot, 0, tid);

    for (int ch = 0; ch < 6; ch++) {
        asm volatile("cp.async.wait_group 0;" ::: "memory");
        __syncthreads();
        if (ch < 5) {
            qkv_load(As[(ch+1)&1], Bs[(ch+1)&1], pt, ot, (ch+1)*32, tid);
        }
        u32 ab = sptr(As[ch & 1]);
        u32 bbs = sptr(Bs[ch & 1]);
        #pragma unroll
        for (int ks = 0; ks < 2; ks++) {
            u32 av[4][4];
            u32 bv[4][2];
            #pragma unroll
            for (int mt = 0; mt < 4; mt++) {
                int row = m0 + mt*16 + (lane & 15);
                u32 ad = ab + (row*40 + ((lane >> 4) & 1)*8 + ks*16)*2;
                ldsm4(av[mt][0], av[mt][1], av[mt][2], av[mt][3], ad);
            }
            #pragma unroll
            for (int n2 = 0; n2 < 2; n2++) {
                int row = n0 + n2*16 + (lane & 7) + ((lane >> 4) & 1)*8;
                u32 ad = bbs + (row*40 + ((lane >> 3) & 1)*8 + ks*16)*2;
                u32 r0;
                u32 r1;
                u32 r2;
                u32 r3;
                ldsm4(r0, r1, r2, r3, ad);
                bv[n2*2+0][0] = r0;
                bv[n2*2+0][1] = r1;
                bv[n2*2+1][0] = r2;
                bv[n2*2+1][1] = r3;
            }
            #pragma unroll
            for (int mt = 0; mt < 4; mt++) {
                #pragma unroll
                for (int nt = 0; nt < 4; nt++) {
                    mma_bf16(acc[mt][nt][0], acc[mt][nt][1], acc[mt][nt][2], acc[mt][nt][3],
                             av[mt][0], av[mt][1], av[mt][2], av[mt][3], bv[nt][0], bv[nt][1]);
                }
            }
        }
    }

    const float qscale = 0.20412414523193154f;
    int lr = lane >> 2;
    int lc = lane & 3;
    #pragma unroll
    for (int mt = 0; mt < 4; mt++) {
        int row = pt + m0 + mt*16 + lr;
        #pragma unroll
        for (int nt = 0; nt < 4; nt++) {
            int col = ot + n0 + nt*8 + 2*lc;
            if (col < 576) {
                float s = (col < C) ? qscale : 1.f;
                __nv_bfloat162 v0;
                v0.x = __float2bfloat16(acc[mt][nt][0] * s);
                v0.y = __float2bfloat16(acc[mt][nt][1] * s);
                *(__nv_bfloat162*)&g_qkvb[(size_t)row*576 + col] = v0;
                __nv_bfloat162 v1;
                v1.x = __float2bfloat16(acc[mt][nt][2] * s);
                v1.y = __float2bfloat16(acc[mt][nt][3] * s);
                *(__nv_bfloat162*)&g_qkvb[(size_t)(row+8)*576 + col] = v1;
            }
        }
    }
}

// ================= K2b: tensor-core window attention (compact smem, 3 CTA/SM) ==================
#define SW 584
__global__ __launch_bounds__(128,3) void k_wattn_t(const float* __restrict__ rpb) {
    extern __shared__ __nv_bfloat16 smw[];
    __shared__ int lab[64];

    int tid = threadIdx.x;
    int lane = tid & 31;
    int warp = tid >> 5;
    int widx = blockIdx.x;
    int pix0 = widx * 64;
    int wy = (widx >> 5) & 31;
    int wx = widx & 31;

    if (tid < 64) {
        int i1 = tid >> 3;
        int j1 = tid & 7;
        int sr = wy*8 + i1;
        int sc = wx*8 + j1;
        lab[tid] = ((sr >= HH-WS) + (sr >= HH-SS))*3 + ((sc >= WW-WS) + (sc >= WW-SS));
    }
    for (int e = tid; e < 4608; e += 128) {
        int row = e / 72;
        int seg = e - row*72;
        cpa16(sptr(&smw[row*SW + seg*8]), g_qkvb + (size_t)(pix0 + row)*576 + seg*8, true);
    }
    asm volatile("cp.async.commit_group;" ::: "memory");
    asm volatile("cp.async.wait_group 0;" ::: "memory");
    __syncthreads();

    int lr = lane >> 2;
    int lc = lane & 3;
    int wrow0 = warp*16;
    int r0 = wrow0 + lr;
    int r1 = r0 + 8;
    int baseA = (((r0 >> 3) + 7)*15 + ((r0 & 7) - 2*lc + 7))*8;
    int baseB = (((r1 >> 3) + 7)*15 + ((r1 & 7) - 2*lc + 7))*8;
    int labA = lab[r0];
    int labB = lab[r1];
    u32 mbits = 0;
    #pragma unroll
    for (int f = 0; f < 8; f++) {
        int cA = f*8 + 2*lc;
        int lA = lab[cA];
        int lB = lab[cA + 1];
        if (labA != lA) { mbits |= 1u << (f*4 + 0); }
        if (labA != lB) { mbits |= 1u << (f*4 + 1); }
        if (labB != lA) { mbits |= 1u << (f*4 + 2); }
        if (labB != lB) { mbits |= 1u << (f*4 + 3); }
    }

    u32 smbase = sptr(smw);
    for (int h = 0; h < NH; h++) {
        int colQ = h*24;
        int colK = 192 + h*24;
        int colV = 384 + h*24;
        float c[8][4];
        #pragma unroll
        for (int f = 0; f < 8; f++) {
            c[f][0] = 0.f; c[f][1] = 0.f; c[f][2] = 0.f; c[f][3] = 0.f;
        }
        {
            u32 aq[4];
            u32 ad = smbase + ((wrow0 + (lane & 15))*SW + colQ + ((lane >> 4) & 1)*8)*2;
            ldsm4(aq[0], aq[1], aq[2], aq[3], ad);
            u32 a80;
            u32 a81;
            u32 ad8 = smbase + ((wrow0 + (lane & 15))*SW + colQ + 16)*2;
            ldsm2(a80, a81, ad8);
            u32 kb[8];
            {
                u32 t0; u32 t1; u32 t2; u32 t3;
                u32 kd0 = smbase + (lane*SW + colK + 16)*2;
                ldsm4(t0, t1, t2, t3, kd0);
                kb[0] = t0; kb[1] = t1; kb[2] = t2; kb[3] = t3;
                u32 kd1 = smbase + ((32 + lane)*SW + colK + 16)*2;
                ldsm4(t0, t1, t2, t3, kd1);
                kb[4] = t0; kb[5] = t1; kb[6] = t2; kb[7] = t3;
            }
            #pragma unroll
            for (int n2 = 0; n2 < 4; n2++) {
                u32 b0;
                u32 b1;
                u32 b2;
                u32 b3;
                u32 bd = smbase + ((n2*16 + (lane & 7) + ((lane >> 4) & 1)*8)*SW
                                   + colK + ((lane >> 3) & 1)*8)*2;
                ldsm4(b0, b1, b2, b3, bd);
                mma_bf16(c[2*n2][0], c[2*n2][1], c[2*n2][2], c[2*n2][3],
                         aq[0], aq[1], aq[2], aq[3], b0, b1);
                mma_bf16(c[2*n2+1][0], c[2*n2+1][1], c[2*n2+1][2], c[2*n2+1][3],
                         aq[0], aq[1], aq[2], aq[3], b2, b3);
                mma_bf16_k8(c[2*n2][0], c[2*n2][1], c[2*n2][2], c[2*n2][3],
                            a80, a81, kb[2*n2]);
                mma_bf16_k8(c[2*n2+1][0], c[2*n2+1][1], c[2*n2+1][2], c[2*n2+1][3],
                            a80, a81, kb[2*n2+1]);
            }
        }
        int hA = baseA + h;
        int hB = baseB + h;
        #pragma unroll
        for (int f = 0; f < 8; f++) {
            c[f][0] += __ldg(&rpb[hA - 120*f])     + (((mbits >> (f*4+0)) & 1) ? -100.f : 0.f);
            c[f][1] += __ldg(&rpb[hA - 120*f - 8]) + (((mbits >> (f*4+1)) & 1) ? -100.f : 0.f);
            c[f][2] += __ldg(&rpb[hB - 120*f])     + (((mbits >> (f*4+2)) & 1) ? -100.f : 0.f);
            c[f][3] += __ldg(&rpb[hB - 120*f - 8]) + (((mbits >> (f*4+3)) & 1) ? -100.f : 0.f);
        }
        float mx0 = -1e30f;
        float mx1 = -1e30f;
        #pragma unroll
        for (int f = 0; f < 8; f++) {
            mx0 = fmaxf(mx0, fmaxf(c[f][0], c[f][1]));
            mx1 = fmaxf(mx1, fmaxf(c[f][2], c[f][3]));
        }
        mx0 = fmaxf(mx0, __shfl_xor_sync(0xffffffffu, mx0, 1));
        mx0 = fmaxf(mx0, __shfl_xor_sync(0xffffffffu, mx0, 2));
        mx1 = fmaxf(mx1, __shfl_xor_sync(0xffffffffu, mx1, 1));
        mx1 = fmaxf(mx1, __shfl_xor_sync(0xffffffffu, mx1, 2));
        float s0 = 0.f;
        float s1 = 0.f;
        #pragma unroll
        for (int f = 0; f < 8; f++) {
            c[f][0] = __expf(c[f][0] - mx0);
            c[f][1] = __expf(c[f][1] - mx0);
            c[f][2] = __expf(c[f][2] - mx1);
            c[f][3] = __expf(c[f][3] - mx1);
            s0 += c[f][0] + c[f][1];
            s1 += c[f][2] + c[f][3];
        }
        s0 += __shfl_xor_sync(0xffffffffu, s0, 1);
        s0 += __shfl_xor_sync(0xffffffffu, s0, 2);
        s1 += __shfl_xor_sync(0xffffffffu, s1, 1);
        s1 += __shfl_xor_sync(0xffffffffu, s1, 2);
        float inv0 = 1.f / s0;
        float inv1 = 1.f / s1;
        u32 ap[4][4];
        #pragma unroll
        for (int j = 0; j < 4; j++) {
            ap[j][0] = packbf(c[2*j][0]*inv0,   c[2*j][1]*inv0);
            ap[j][1] = packbf(c[2*j][2]*inv1,   c[2*j][3]*inv1);
            ap[j][2] = packbf(c[2*j+1][0]*inv0, c[2*j+1][1]*inv0);
            ap[j][3] = packbf(c[2*j+1][2]*inv1, c[2*j+1][3]*inv1);
        }
        float o[3][4];
        #pragma unroll
        for (int nt = 0; nt < 3; nt++) {
            o[nt][0] = 0.f; o[nt][1] = 0.f; o[nt][2] = 0.f; o[nt][3] = 0.f;
        }
        #pragma unroll
        for (int j = 0; j < 4; j++) {
            u32 lo0; u32 lo1; u32 lo2; u32 lo3;
            u32 hi0; u32 hi1; u32 hi2; u32 hi3;
            u32 vlo = smbase + ((j*16 + (lane & 7))*SW + colV + (lane >> 3)*8)*2;
            u32 vhi = smbase + ((j*16 + 8 + (lane & 7))*SW + colV + (lane >> 3)*8)*2;
            ldsm4t(lo0, lo1, lo2, lo3, vlo);
            ldsm4t(hi0, hi1, hi2, hi3, vhi);
            mma_bf16(o[0][0], o[0][1], o[0][2], o[0][3], ap[j][0], ap[j][1], ap[j][2], ap[j][3], lo0, hi0);
            mma_bf16(o[1][0], o[1][1], o[1][2], o[1][3], ap[j][0], ap[j][1], ap[j][2], ap[j][3], lo1, hi1);
            mma_bf16(o[2][0], o[2][1], o[2][2], o[2][3], ap[j][0], ap[j][1], ap[j][2], ap[j][3], lo2, hi2);
        }
        #pragma unroll
        for (int nt = 0; nt < 3; nt++) {
            int col = h*24 + nt*8 + 2*lc;
            __nv_bfloat162 v0;
            v0.x = __float2bfloat16(o[nt][0]);
            v0.y = __float2bfloat16(o[nt][1]);
            *(__nv_bfloat162*)&g_attnb[(size_t)(pix0 + r0)*C + col] = v0;
            __nv_bfloat162 v1;
            v1.x = __float2bfloat16(o[nt][2]);
            v1.y = __float2bfloat16(o[nt][3]);
            *(__nv_bfloat162*)&g_attnb[(size_t)(pix0 + r1)*C + col] = v1;
        }
    }
}

// ================= K2c: proj GEMM bf16 + bias + residual ==================
__global__ __launch_bounds__(256,2) void k_proj_b(const float* __restrict__ pb) {
    __shared__ __align__(16) __nv_bfloat16 As[2][5120];
    __shared__ __align__(16) __nv_bfloat16 Bs[2][2560];
    int pt = blockIdx.y*128;
    int ct = blockIdx.x*64;
    int tid = threadIdx.x;
    int lane = tid & 31;
    int warp = tid >> 5;
    int m0 = (warp & 3)*32;
    int n0 = (warp >> 2)*32;
    float acc[2][4][4] = {};

    proj_load(As[0], Bs[0], pt, ct, 0, tid);

    for (int ch = 0; ch < 6; ch++) {
        asm volatile("cp.async.wait_group 0;" ::: "memory");
        __syncthreads();
        if (ch < 5) {
            proj_load(As[(ch+1)&1], Bs[(ch+1)&1], pt, ct, (ch+1)*32, tid);
        }
        u32 ab = sptr(As[ch & 1]);
        u32 bbs = sptr(Bs[ch & 1]);
        #pragma unroll
        for (int ks = 0; ks < 2; ks++) {
            u32 av[2][4];
            u32 bv[4][2];
            #pragma unroll
            for (int mt = 0; mt < 2; mt++) {
                int row = m0 + mt*16 + (lane & 15);
                u32 ad = ab + (row*40 + ((lane >> 4) & 1)*8 + ks*16)*2;
                ldsm4(av[mt][0], av[mt][1], av[mt][2], av[mt][3], ad);
            }
            #pragma unroll
            for (int n2 = 0; n2 < 2; n2++) {
                int row = n0 + n2*16 + (lane & 7) + ((lane >> 4) & 1)*8;
                u32 ad = bbs + (row*40 + ((lane >> 3) & 1)*8 + ks*16)*2;
                u32 r0;
                u32 r1;
                u32 r2;
                u32 r3;
                ldsm4(r0, r1, r2, r3, ad);
                bv[n2*2+0][0] = r0;
                bv[n2*2+0][1] = r1;
                bv[n2*2+1][0] = r2;
                bv[n2*2+1][1] = r3;
            }
            #pragma unroll
            for (int mt = 0; mt < 2; mt++) {
                #pragma unroll
                for (int nt = 0; nt < 4; nt++) {
                    mma_bf16(acc[mt][nt][0], acc[mt][nt][1], acc[mt][nt][2], acc[mt][nt][3],
                             av[mt][0], av[mt][1], av[mt][2], av[mt][3], bv[nt][0], bv[nt][1]);
                }
            }
        }
    }

    int lr = lane >> 2;
    int lc = lane & 3;
    #pragma unroll
    for (int mt = 0; mt < 2; mt++) {
        #pragma unroll
        for (int half = 0; half < 2; half++) {
            int row = pt + m0 + mt*16 + lr + half*8;
            int bb = row >> 16;
            int widx = (row >> 6) & 1023;
            int tok = row & 63;
            int r = (((widx >> 5) << 3) + (tok >> 3) + SS) & 255;
            int c2 = (((widx & 31) << 3) + (tok & 7) + SS) & 255;
            int gbase = ((bb*HH + r)*WW + c2)*C;
            #pragma unroll
            for (int nt = 0; nt < 4; nt++) {
                int col = ct + n0 + nt*8 + 2*lc;
                float2 v;
                v.x = acc[mt][nt][half*2+0] + pb[col] + g_xt[gbase + col];
                v.y = acc[mt][nt][half*2+1] + pb[col+1] + g_xt[gbase + col + 1];
                *(float2*)&g_x2[gbase + col] = v;
            }
        }
    }
}

// ================= K3: LN2 -> bf16 ==================
__global__ __launch_bounds__(256) void k_ln2(const float* __restrict__ w,
                                             const float* __restrict__ b) {
    int pix = blockIdx.x*8 + (threadIdx.x >> 5);
    int lane = threadIdx.x & 31;
    const float* row = g_x2 + (size_t)pix*C;
    float v[6];
    float sum = 0.f;
    float sq = 0.f;
    #pragma unroll
    for (int i = 0; i < 6; i++) {
        v[i] = row[lane + 32*i];
        sum += v[i];
        sq += v[i]*v[i];
    }
    #pragma unroll
    for (int o = 16; o; o >>= 1) {
        sum += __shfl_xor_sync(0xffffffffu, sum, o);
        sq  += __shfl_xor_sync(0xffffffffu, sq, o);
    }
    float mu = sum / C;
    float rv = rsqrtf(sq / C - mu*mu + 1e-5f);
    __nv_bfloat16* outp = g_ynb + (size_t)pix*C;
    #pragma unroll
    for (int i = 0; i < 6; i++) {
        int c = lane + 32*i;
        outp[c] = __float2bfloat16((v[i]-mu)*rv*w[c] + b[c]);
    }
}

// ================= K4: pin GEMM bf16 (131072 x 1020 x 192) ==================
__global__ __launch_bounds__(256,2) void k_pin_b() {
    __shared__ __align__(16) __nv_bfloat16 As[2][5120];
    __shared__ __align__(16) __nv_bfloat16 Bs[2][5120];
    int pt = blockIdx.y*128;
    int ot = blockIdx.x*128;
    int tid = threadIdx.x;
    int lane = tid & 31;
    int warp = tid >> 5;
    int m0 = (warp >> 2)*64;
    int n0 = (warp & 3)*32;
    float acc[4][4][4] = {};

    pin_load(As[0], Bs[0], pt, ot, 0, tid);

    for (int ch = 0; ch < 6; ch++) {
        asm volatile("cp.async.wait_group 0;" ::: "memory");
        __syncthreads();
        if (ch < 5) {
            pin_load(As[(ch+1)&1], Bs[(ch+1)&1], pt, ot, (ch+1)*32, tid);
        }
        u32 ab = sptr(As[ch & 1]);
        u32 bbs = sptr(Bs[ch & 1]);
        #pragma unroll
        for (int ks = 0; ks < 2; ks++) {
            u32 av[4][4];
            u32 bv[4][2];
            #pragma unroll
            for (int mt = 0; mt < 4; mt++) {
                int row = m0 + mt*16 + (lane & 15);
                u32 ad = ab + (row*40 + ((lane >> 4) & 1)*8 + ks*16)*2;
                ldsm4(av[mt][0], av[mt][1], av[mt][2], av[mt][3], ad);
            }
            #pragma unroll
            for (int n2 = 0; n2 < 2; n2++) {
                int row = n0 + n2*16 + (lane & 7) + ((lane >> 4) & 1)*8;
                u32 ad = bbs + (row*40 + ((lane >> 3) & 1)*8 + ks*16)*2;
                u32 r0;
                u32 r1;
                u32 r2;
                u32 r3;
                ldsm4(r0, r1, r2, r3, ad);
                bv[n2*2+0][0] = r0;
                bv[n2*2+0][1] = r1;
                bv[n2*2+1][0] = r2;
                bv[n2*2+1][1] = r3;
            }
            #pragma unroll
            for (int mt = 0; mt < 4; mt++) {
                #pragma unroll
                for (int nt = 0; nt < 4; nt++) {
                    mma_bf16(acc[mt][nt][0], acc[mt][nt][1], acc[mt][nt][2], acc[mt][nt][3],
                             av[mt][0], av[mt][1], av[mt][2], av[mt][3], bv[nt][0], bv[nt][1]);
                }
            }
        }
    }

    int lr = lane >> 2;
    int lc = lane & 3;
    #pragma unroll
    for (int mt = 0; mt < 4; mt++) {
        int row = pt + m0 + mt*16 + lr;
        #pragma unroll
        for (int nt = 0; nt < 4; nt++) {
            int col = ot + n0 + nt*8 + 2*lc;
            if (col < HID2) {
                __nv_bfloat162 v0;
                v0.x = __float2bfloat16(acc[mt][nt][0]);
                v0.y = __float2bfloat16(acc[mt][nt][1]);
                *(__nv_bfloat162*)&g_y[(size_t)row*HID2 + col] = v0;
                __nv_bfloat162 v1;
                v1.x = __float2bfloat16(acc[mt][nt][2]);
                v1.y = __float2bfloat16(acc[mt][nt][3]);
                *(__nv_bfloat162*)&g_y[(size_t)(row+8)*HID2 + col] = v1;
            }
        }
    }
}

// ================= K5: depthwise 3x3 + gated GELU (f32x2 packed FMA) ==================
__global__ __launch_bounds__(256) void k_dw2(const float* __restrict__ dw) {
    int bx = blockIdx.x;
    int t = threadIdx.x;
    int xseg = (bx & 63) * 4;
    int r = (bx >> 6) & 255;
    int bb = bx >> 14;
    size_t prow = (size_t)(bb*HH + r)*WW;
    if (t >= 255) {
        if (t == 255) {
            #pragma unroll
            for (int o = 0; o < 4; o++) {
                *(u32*)&g_gg[(prow + xseg + o)*512 + 510] = 0u;
            }
        }
        return;
    }
    int c = t*2;
    u64 ya[3][6];
    u64 yb[3][6];
    #pragma unroll
    for (int dy = 0; dy < 3; dy++) {
        int rowi = r + dy - 1;
        bool rok = (unsigned)rowi < 256u;
        #pragma unroll
        for (int dx = 0; dx < 6; dx++) {
            int col = xseg + dx - 1;
            bool ok = rok && ((unsigned)col < 256u);
            float2 va = make_float2(0.f, 0.f);
            float2 vb = make_float2(0.f, 0.f);
            if (ok) {
                size_t base = ((size_t)(bb*HH + rowi)*WW + col)*HID2;
                va = __bfloat1622float2(*(const __nv_bfloat162*)&g_y[base + c]);
                vb = __bfloat1622float2(*(const __nv_bfloat162*)&g_y[base + c + HID]);
            }
            ya[dy][dx] = pk2(va.x, va.y);
            yb[dy][dx] = pk2(vb.x, vb.y);
        }
    }
    u64 wA[9];
    u64 wB[9];
    #pragma unroll
    for (int q = 0; q < 9; q++) {
        wA[q] = pk2(dw[c*9 + q], dw[(c+1)*9 + q]);
        wB[q] = pk2(dw[(c+HID)*9 + q], dw[(c+HID+1)*9 + q]);
    }
    const u64 zero2 = pk2(0.f, 0.f);
    #pragma unroll
    for (int o = 0; o < 4; o++) {
        u64 sa = zero2;
        u64 sb = zero2;
        #pragma unroll
        for (int ky = 0; ky < 3; ky++) {
            #pragma unroll
            for (int kx = 0; kx < 3; kx++) {
                int q = ky*3 + kx;
                sa = fma2(wA[q], ya[ky][o+kx], sa);
                sb = fma2(wB[q], yb[ky][o+kx], sb);
            }
        }
        float s0;
        float s1;
        upk2(s0, s1, sa);
        float g0;
        float g1;
        upk2(g0, g1, sb);
        float e0 = 0.5f*s0*(1.f + erff(s0*0.70710678118654752f)) * g0;
        float e1 = 0.5f*s1*(1.f + erff(s1*0.70710678118654752f)) * g1;
        *(__nv_bfloat162*)&g_gg[(prow + xseg + o)*512 + c] = __floats2bfloat162_rn(e0, e1);
    }
}

// ================= K6: pout GEMM bf16 + residual -> NCHW ==================
#define SPP 132
__global__ __launch_bounds__(256,2) void k_pout_b(float* __restrict__ outp) {
    __shared__ __align__(16) float smem_f[8448];
    __nv_bfloat16* As = (__nv_bfloat16*)smem_f;
    __nv_bfloat16* Bs = (__nv_bfloat16*)(smem_f + 5120);
    float* Cs = smem_f;
    int pt = blockIdx.y*128;
    int ct = blockIdx.x*64;
    int tid = threadIdx.x;
    int lane = tid & 31;
    int warp = tid >> 5;
    int m0 = (warp & 3)*32;
    int n0 = (warp >> 2)*32;
    float acc[2][4][4] = {};

    pout_load(As, Bs, pt, ct, 0, tid);

    for (int ch = 0; ch < 16; ch++) {
        asm volatile("cp.async.wait_group 0;" ::: "memory");
        __syncthreads();
        if (ch < 15) {
            int st = (ch+1) & 1;
            pout_load(As + st*5120, Bs + st*2560, pt, ct, (ch+1)*32, tid);
        }
        u32 ab = sptr(As + (ch & 1)*5120);
        u32 bbs = sptr(Bs + (ch & 1)*2560);
        #pragma unroll
        for (int ks = 0; ks < 2; ks++) {
            u32 av[2][4];
            u32 bv[4][2];
            #pragma unroll
            for (int mt = 0; mt < 2; mt++) {
                int row = m0 + mt*16 + (lane & 15);
                u32 ad = ab + (row*40 + ((lane >> 4) & 1)*8 + ks*16)*2;
                ldsm4(av[mt][0], av[mt][1], av[mt][2], av[mt][3], ad);
            }
            #pragma unroll
            for (int n2 = 0; n2 < 2; n2++) {
                int row = n0 + n2*16 + (lane & 7) + ((lane >> 4) & 1)*8;
                u32 ad = bbs + (row*40 + ((lane >> 3) & 1)*8 + ks*16)*2;
                u32 r0;
                u32 r1;
                u32 r2;
                u32 r3;
                ldsm4(r0, r1, r2, r3, ad);
                bv[n2*2+0][0] = r0;
                bv[n2*2+0][1] = r1;
                bv[n2*2+1][0] = r2;
                bv[n2*2+1][1] = r3;
            }
            #pragma unroll
            for (int mt = 0; mt < 2; mt++) {
                #pragma unroll
                for (int nt = 0; nt < 4; nt++) {
                    mma_bf16(acc[mt][nt][0], acc[mt][nt][1], acc[mt][nt][2], acc[mt][nt][3],
                             av[mt][0], av[mt][1], av[mt][2], av[mt][3], bv[nt][0], bv[nt][1]);
                }
            }
        }
    }
    __syncthreads();

    int lr = lane >> 2;
    int lc = lane & 3;
    #pragma unroll
    for (int mt = 0; mt < 2; mt++) {
        int row = m0 + mt*16 + lr;
        #pragma unroll
        for (int nt = 0; nt < 4; nt++) {
            int col = n0 + nt*8 + 2*lc;
            Cs[col*SPP + row] = acc[mt][nt][0];
            Cs[(col+1)*SPP + row] = acc[mt][nt][1];
            Cs[col*SPP + row + 8] = acc[mt][nt][2];
            Cs[(col+1)*SPP + row + 8] = acc[mt][nt][3];
        }
    }
    __syncthreads();
    for (int e = tid; e < 2048; e += 256) {
        int p = e >> 4;
        int c4 = e & 15;
        float4 v = *(const float4*)&g_x2[(size_t)(pt + p)*C + ct + c4*4];
        Cs[(c4*4+0)*SPP + p] += v.x;
        Cs[(c4*4+1)*SPP + p] += v.y;
        Cs[(c4*4+2)*SPP + p] += v.z;
        Cs[(c4*4+3)*SPP + p] += v.w;
    }
    __syncthreads();
    int bb = pt >> 16;
    int hw0 = pt & 65535;
    for (int e = tid; e < 2048; e += 256) {
        int c = e >> 5;
        int p4 = e & 31;
        float4 v = *(const float4*)&Cs[c*SPP + p4*4];
        *(float4*)&outp[((size_t)(bb*C + ct + c))*HW + hw0 + p4*4] = v;
    }
}

// ================= launch ==================
extern "C" void kernel_launch(void* const* d_in, const int* in_sizes, int n_in,
                              void* d_out, int out_size) {
    const float* x      = (const float*)d_in[0];
    const float* n1w    = (const float*)d_in[1];
    const float* n1b    = (const float*)d_in[2];
    const float* qkv_w  = (const float*)d_in[3];
    const float* rpb    = (const float*)d_in[4];
    const float* proj_w = (const float*)d_in[5];
    const float* proj_b = (const float*)d_in[6];
    const float* n2w    = (const float*)d_in[7];
    const float* n2b    = (const float*)d_in[8];
    const float* pin_w  = (const float*)d_in[9];
    const float* dw_w   = (const float*)d_in[10];
    const float* pout_w = (const float*)d_in[11];
    float* outp = (float*)d_out;

    const int wattn_smem = 64*SW*2;   // 74752
    cudaFuncSetAttribute(k_wattn_t, cudaFuncAttributeMaxDynamicSharedMemorySize, wattn_smem);

    const int cvt_total = 576*C + C*C + HID2*C + C*512;
    k_cvt_all<<<(cvt_total + 255)/256, 256>>>(qkv_w, proj_w, pin_w, pout_w);
    k_ln1    <<<NPIX/32, 256>>>(x, n1w, n1b);
    k_qkv_b  <<<dim3(5, NPIX/128), 256>>>();
    k_wattn_t<<<2048, 128, wattn_smem>>>(rpb);
    k_proj_b <<<dim3(3, NPIX/128), 256>>>(proj_b);
    k_ln2    <<<NPIX/8, 256>>>(n2w, n2b);
    k_pin_b  <<<dim3(8, NPIX/128), 256>>>();
    k_dw2    <<<BATCH*HH*(WW/4), 256>>>(dw_w);
    k_pout_b <<<dim3(3, NPIX/128), 256>>>(outp);
}

// round 12
// speedup vs baseline: 1.1201x; 1.0567x over previous
#include <cuda_runtime.h>
#include <cuda_bf16.h>
#include <stdint.h>
#include <math.h>

typedef unsigned int u32;
typedef unsigned long long u64;

#define BATCH 2
#define C 192
#define HH 256
#define WW 256
#define HW (HH*WW)
#define NPIX (BATCH*HW)
#define NH 8
#define HD 24
#define WS 8
#define SS 4
#define HID 510
#define HID2 1020

// ---- scratch ----
__device__ float g_xt[NPIX*C];
__device__ float g_x2[NPIX*C];
__device__ __nv_bfloat16 g_xnb[(size_t)NPIX*C];
__device__ __nv_bfloat16 g_qkvb[(size_t)NPIX*576];
__device__ __nv_bfloat16 g_attnb[(size_t)NPIX*C];
__device__ __nv_bfloat16 g_ynb[(size_t)NPIX*C];
__device__ __nv_bfloat16 g_y[(size_t)NPIX*HID2];
__device__ __nv_bfloat16 g_gg[(size_t)NPIX*512];
__device__ __nv_bfloat16 g_qkvw[576*C];
__device__ __nv_bfloat16 g_projw[C*C];
__device__ __nv_bfloat16 g_pinb[HID2*C];
__device__ __nv_bfloat16 g_poutb[C*512];

__device__ __forceinline__ u32 sptr(const void* p) {
    return (u32)__cvta_generic_to_shared(p);
}
__device__ __forceinline__ void cpa16(u32 dst, const void* src, bool full) {
    int sz = full ? 16 : 0;
    asm volatile("cp.async.cg.shared.global [%0], [%1], 16, %2;" :: "r"(dst), "l"(src), "r"(sz));
}
__device__ __forceinline__ void cpwait(bool last) {
    if (last) {
        asm volatile("cp.async.wait_group 0;" ::: "memory");
    } else {
        asm volatile("cp.async.wait_group 1;" ::: "memory");
    }
}
__device__ __forceinline__ void ldsm4(u32& r0, u32& r1, u32& r2, u32& r3, u32 a) {
    asm volatile("ldmatrix.sync.aligned.m8n8.x4.shared.b16 {%0,%1,%2,%3}, [%4];"
        : "=r"(r0), "=r"(r1), "=r"(r2), "=r"(r3) : "r"(a));
}
__device__ __forceinline__ void ldsm2(u32& r0, u32& r1, u32 a) {
    asm volatile("ldmatrix.sync.aligned.m8n8.x2.shared.b16 {%0,%1}, [%2];"
        : "=r"(r0), "=r"(r1) : "r"(a));
}
__device__ __forceinline__ void ldsm4t(u32& r0, u32& r1, u32& r2, u32& r3, u32 a) {
    asm volatile("ldmatrix.sync.aligned.m8n8.x4.trans.shared.b16 {%0,%1,%2,%3}, [%4];"
        : "=r"(r0), "=r"(r1), "=r"(r2), "=r"(r3) : "r"(a));
}
__device__ __forceinline__ void mma_bf16(float& c0, float& c1, float& c2, float& c3,
    u32 a0, u32 a1, u32 a2, u32 a3, u32 b0, u32 b1) {
    asm volatile("mma.sync.aligned.m16n8k16.row.col.f32.bf16.bf16.f32 "
        "{%0,%1,%2,%3}, {%4,%5,%6,%7}, {%8,%9}, {%0,%1,%2,%3};"
        : "+f"(c0), "+f"(c1), "+f"(c2), "+f"(c3)
        : "r"(a0), "r"(a1), "r"(a2), "r"(a3), "r"(b0), "r"(b1));
}
__device__ __forceinline__ void mma_bf16_k8(float& c0, float& c1, float& c2, float& c3,
    u32 a0, u32 a1, u32 b0) {
    asm volatile("mma.sync.aligned.m16n8k8.row.col.f32.bf16.bf16.f32 "
        "{%0,%1,%2,%3}, {%4,%5}, {%6}, {%0,%1,%2,%3};"
        : "+f"(c0), "+f"(c1), "+f"(c2), "+f"(c3)
        : "r"(a0), "r"(a1), "r"(b0));
}
__device__ __forceinline__ u32 packbf(float a, float b) {
    __nv_bfloat162 t = __floats2bfloat162_rn(a, b);
    return *(u32*)&t;
}
__device__ __forceinline__ u64 pk2(float x, float y) {
    u64 r;
    asm("mov.b64 %0, {%1,%2};" : "=l"(r) : "f"(x), "f"(y));
    return r;
}
__device__ __forceinline__ void upk2(float& x, float& y, u64 v) {
    asm("mov.b64 {%0,%1}, %2;" : "=f"(x), "=f"(y) : "l"(v));
}
__device__ __forceinline__ u64 fma2(u64 a, u64 b, u64 c) {
    u64 d;
    asm("fma.rn.f32x2 %0, %1, %2, %3;" : "=l"(d) : "l"(a), "l"(b), "l"(c));
    return d;
}

// ================= merged weight convert ==================
__global__ void k_cvt_all(const float* __restrict__ qkvw, const float* __restrict__ projw,
                          const float* __restrict__ pinw, const float* __restrict__ poutw) {
    int i = blockIdx.x*256 + threadIdx.x;
    if (i < 576*C) {
        g_qkvw[i] = __float2bfloat16(qkvw[i]);
        return;
    }
    i -= 576*C;
    if (i < C*C) {
        g_projw[i] = __float2bfloat16(projw[i]);
        return;
    }
    i -= C*C;
    if (i < HID2*C) {
        g_pinb[i] = __float2bfloat16(pinw[i]);
        return;
    }
    i -= HID2*C;
    if (i < C*512) {
        int o = i >> 9;
        int k = i & 511;
        g_poutb[i] = __float2bfloat16(k < HID ? poutw[o*HID + k] : 0.f);
    }
}

// ================= K1: LN1 + transpose + window-permuted bf16 ==================
__global__ __launch_bounds__(256) void k_ln1(const float* __restrict__ x,
        const float* __restrict__ w, const float* __restrict__ b) {
    __shared__ float s[C*33];
    __shared__ float smu[32];
    __shared__ float srv[32];
    __shared__ int slot_s[32];
    int pix0 = blockIdx.x * 32;
    int bb = pix0 / HW;
    int hw0 = pix0 % HW;
    for (int e = threadIdx.x; e < C*32; e += 256) {
        int c = e >> 5;
        int p = e & 31;
        s[c*33 + p] = x[(size_t)(bb*C + c)*HW + hw0 + p];
    }
    __syncthreads();
    {
        int lane = threadIdx.x & 31;
        int warp = threadIdx.x >> 5;
        #pragma unroll
        for (int pp = 0; pp < 4; pp++) {
            int p = warp*4 + pp;
            float sum = 0.f;
            float sq = 0.f;
            #pragma unroll
            for (int i = 0; i < 6; i++) {
                float v = s[(lane + 32*i)*33 + p];
                sum += v;
                sq += v*v;
            }
            #pragma unroll
            for (int o = 16; o; o >>= 1) {
                sum += __shfl_xor_sync(0xffffffffu, sum, o);
                sq  += __shfl_xor_sync(0xffffffffu, sq, o);
            }
            if (lane == 0) {
                float mu = sum / C;
                smu[p] = mu;
                srv[p] = rsqrtf(sq / C - mu*mu + 1e-5f);
            }
        }
    }
    if (threadIdx.x < 32) {
        int p = threadIdx.x;
        int hw = hw0 + p;
        int r = hw >> 8;
        int cc = hw & 255;
        int sr = (r - SS + 256) & 255;
        int sc = (cc - SS + 256) & 255;
        slot_s[p] = (((bb << 10) + ((sr >> 3) << 5) + (sc >> 3)) << 6) + ((sr & 7) << 3) + (sc & 7);
    }
    __syncthreads();
    for (int e = threadIdx.x; e < C*32; e += 256) {
        int p = e / C;
        int c = e % C;
        float v = s[c*33 + p];
        g_xt[(pix0 + p)*C + c] = v;
        float ln = (v - smu[p]) * srv[p] * w[c] + b[c];
        g_xnb[(size_t)slot_s[p]*C + c] = __float2bfloat16(ln);
    }
}

// ================= tile loaders ==================
__device__ __forceinline__ void qkv_load(__nv_bfloat16* Adst, __nv_bfloat16* Bdst,
                                         int pt, int ot, int k0, int tid) {
    #pragma unroll
    for (int i = 0; i < 2; i++) {
        int e = tid + i*256;
        int row = e >> 2;
        int seg = e & 3;
        cpa16(sptr(Adst + row*40 + seg*8), g_xnb + (size_t)(pt + row)*C + k0 + seg*8, true);
        int og = ot + row;
        bool ok = og < 576;
        cpa16(sptr(Bdst + row*40 + seg*8), g_qkvw + (size_t)(ok ? og : 0)*C + k0 + seg*8, ok);
    }
    asm volatile("cp.async.commit_group;" ::: "memory");
}

__device__ __forceinline__ void proj_load(__nv_bfloat16* Adst, __nv_bfloat16* Bdst,
                                          int pt, int ct, int k0, int tid) {
    #pragma unroll
    for (int i = 0; i < 2; i++) {
        int e = tid + i*256;
        int row = e >> 2;
        int seg = e & 3;
        cpa16(sptr(Adst + row*40 + seg*8), g_attnb + (size_t)(pt + row)*C + k0 + seg*8, true);
    }
    int row = tid >> 2;
    int seg = tid & 3;
    cpa16(sptr(Bdst + row*40 + seg*8), g_projw + (size_t)(ct + row)*C + k0 + seg*8, true);
    asm volatile("cp.async.commit_group;" ::: "memory");
}

__device__ __forceinline__ void pin_load(__nv_bfloat16* Adst, __nv_bfloat16* Bdst,
                                         int pt, int ot, int k0, int tid) {
    #pragma unroll
    for (int i = 0; i < 2; i++) {
        int e = tid + i*256;
        int row = e >> 2;
        int seg = e & 3;
        cpa16(sptr(Adst + row*40 + seg*8), g_ynb + (size_t)(pt + row)*C + k0 + seg*8, true);
        int og = ot + row;
        bool ok = og < HID2;
        cpa16(sptr(Bdst + row*40 + seg*8), g_pinb + (size_t)(ok ? og : 0)*C + k0 + seg*8, ok);
    }
    asm volatile("cp.async.commit_group;" ::: "memory");
}

__device__ __forceinline__ void pout_load(__nv_bfloat16* Adst, __nv_bfloat16* Bdst,
                                          int pt, int ct, int k0, int tid) {
    #pragma unroll
    for (int i = 0; i < 2; i++) {
        int e = tid + i*256;
        int row = e >> 2;
        int seg = e & 3;
        cpa16(sptr(Adst + row*40 + seg*8), g_gg + (size_t)(pt + row)*512 + k0 + seg*8, true);
    }
    int row = tid >> 2;
    int seg = tid & 3;
    cpa16(sptr(Bdst + row*40 + seg*8), g_poutb + (size_t)(ct + row)*512 + k0 + seg*8, true);
    asm volatile("cp.async.commit_group;" ::: "memory");
}

// ================= K2a: QKV GEMM bf16 (131072 x 576 x 192), 3-stage ==================
__global__ __launch_bounds__(256,2) void k_qkv_b() {
    extern __shared__ __nv_bfloat16 smq[];
    __nv_bfloat16* As = smq;           // 3 x 5120
    __nv_bfloat16* Bs = smq + 15360;   // 3 x 5120
    int pt = blockIdx.y*128;
    int ot = blockIdx.x*128;
    int tid = threadIdx.x;
    int lane = tid & 31;
    int warp = tid >> 5;
    int m0 = (warp >> 2)*64;
    int n0 = (warp & 3)*32;
    float acc[4][4][4] = {};

    qkv_load(As, Bs, pt, ot, 0, tid);
    qkv_load(As + 5120, Bs + 5120, pt, ot, 32, tid);

    for (int ch = 0; ch < 6; ch++) {
        cpwait(ch == 5);
        __syncthreads();
        if (ch + 2 < 6) {
            int st = (ch + 2) % 3;
            qkv_load(As + st*5120, Bs + st*5120, pt, ot, (ch+2)*32, tid);
        }
        int cb = ch % 3;
        u32 ab = sptr(As + cb*5120);
        u32 bbs = sptr(Bs + cb*5120);
        #pragma unroll
        for (int ks = 0; ks < 2; ks++) {
            u32 av[4][4];
            u32 bv[4][2];
            #pragma unroll
            for (int mt = 0; mt < 4; mt++) {
                int row = m0 + mt*16 + (lane & 15);
                u32 ad = ab + (row*40 + ((lane >> 4) & 1)*8 + ks*16)*2;
                ldsm4(av[mt][0], av[mt][1], av[mt][2], av[mt][3], ad);
            }
            #pragma unroll
            for (int n2 = 0; n2 < 2; n2++) {
                int row = n0 + n2*16 + (lane & 7) + ((lane >> 4) & 1)*8;
                u32 ad = bbs + (row*40 + ((lane >> 3) & 1)*8 + ks*16)*2;
                u32 r0;
                u32 r1;
                u32 r2;
                u32 r3;
                ldsm4(r0, r1, r2, r3, ad);
                bv[n2*2+0][0] = r0;
                bv[n2*2+0][1] = r1;
                bv[n2*2+1][0] = r2;
                bv[n2*2+1][1] = r3;
            }
            #pragma unroll
            for (int mt = 0; mt < 4; mt++) {
                #pragma unroll
                for (int nt = 0; nt < 4; nt++) {
                    mma_bf16(acc[mt][nt][0], acc[mt][nt][1], acc[mt][nt][2], acc[mt][nt][3],
                             av[mt][0], av[mt][1], av[mt][2], av[mt][3], bv[nt][0], bv[nt][1]);
                }
            }
        }
    }

    const float qscale = 0.20412414523193154f;
    int lr = lane >> 2;
    int lc = lane & 3;
    #pragma unroll
    for (int mt = 0; mt < 4; mt++) {
        int row = pt + m0 + mt*16 + lr;
        #pragma unroll
        for (int nt = 0; nt < 4; nt++) {
            int col = ot + n0 + nt*8 + 2*lc;
            if (col < 576) {
                float s = (col < C) ? qscale : 1.f;
                __nv_bfloat162 v0;
                v0.x = __float2bfloat16(acc[mt][nt][0] * s);
                v0.y = __float2bfloat16(acc[mt][nt][1] * s);
                *(__nv_bfloat162*)&g_qkvb[(size_t)row*576 + col] = v0;
                __nv_bfloat162 v1;
                v1.x = __float2bfloat16(acc[mt][nt][2] * s);
                v1.y = __float2bfloat16(acc[mt][nt][3] * s);
                *(__nv_bfloat162*)&g_qkvb[(size_t)(row+8)*576 + col] = v1;
            }
        }
    }
}

// ================= K2b: tensor-core window attention ==================
#define SW 584
__global__ __launch_bounds__(128,3) void k_wattn_t(const float* __restrict__ rpb) {
    extern __shared__ __nv_bfloat16 smw[];
    __shared__ int lab[64];

    int tid = threadIdx.x;
    int lane = tid & 31;
    int warp = tid >> 5;
    int widx = blockIdx.x;
    int pix0 = widx * 64;
    int wy = (widx >> 5) & 31;
    int wx = widx & 31;

    if (tid < 64) {
        int i1 = tid >> 3;
        int j1 = tid & 7;
        int sr = wy*8 + i1;
        int sc = wx*8 + j1;
        lab[tid] = ((sr >= HH-WS) + (sr >= HH-SS))*3 + ((sc >= WW-WS) + (sc >= WW-SS));
    }
    for (int e = tid; e < 4608; e += 128) {
        int row = e / 72;
        int seg = e - row*72;
        cpa16(sptr(&smw[row*SW + seg*8]), g_qkvb + (size_t)(pix0 + row)*576 + seg*8, true);
    }
    asm volatile("cp.async.commit_group;" ::: "memory");
    asm volatile("cp.async.wait_group 0;" ::: "memory");
    __syncthreads();

    int lr = lane >> 2;
    int lc = lane & 3;
    int wrow0 = warp*16;
    int r0 = wrow0 + lr;
    int r1 = r0 + 8;
    int baseA = (((r0 >> 3) + 7)*15 + ((r0 & 7) - 2*lc + 7))*8;
    int baseB = (((r1 >> 3) + 7)*15 + ((r1 & 7) - 2*lc + 7))*8;
    int labA = lab[r0];
    int labB = lab[r1];
    u32 mbits = 0;
    #pragma unroll
    for (int f = 0; f < 8; f++) {
        int cA = f*8 + 2*lc;
        int lA = lab[cA];
        int lB = lab[cA + 1];
        if (labA != lA) { mbits |= 1u << (f*4 + 0); }
        if (labA != lB) { mbits |= 1u << (f*4 + 1); }
        if (labB != lA) { mbits |= 1u << (f*4 + 2); }
        if (labB != lB) { mbits |= 1u << (f*4 + 3); }
    }

    u32 smbase = sptr(smw);
    for (int h = 0; h < NH; h++) {
        int colQ = h*24;
        int colK = 192 + h*24;
        int colV = 384 + h*24;
        float c[8][4];
        #pragma unroll
        for (int f = 0; f < 8; f++) {
            c[f][0] = 0.f; c[f][1] = 0.f; c[f][2] = 0.f; c[f][3] = 0.f;
        }
        {
            u32 aq[4];
            u32 ad = smbase + ((wrow0 + (lane & 15))*SW + colQ + ((lane >> 4) & 1)*8)*2;
            ldsm4(aq[0], aq[1], aq[2], aq[3], ad);
            u32 a80;
            u32 a81;
            u32 ad8 = smbase + ((wrow0 + (lane & 15))*SW + colQ + 16)*2;
            ldsm2(a80, a81, ad8);
            u32 kb[8];
            {
                u32 t0; u32 t1; u32 t2; u32 t3;
                u32 kd0 = smbase + (lane*SW + colK + 16)*2;
                ldsm4(t0, t1, t2, t3, kd0);
                kb[0] = t0; kb[1] = t1; kb[2] = t2; kb[3] = t3;
                u32 kd1 = smbase + ((32 + lane)*SW + colK + 16)*2;
                ldsm4(t0, t1, t2, t3, kd1);
                kb[4] = t0; kb[5] = t1; kb[6] = t2; kb[7] = t3;
            }
            #pragma unroll
            for (int n2 = 0; n2 < 4; n2++) {
                u32 b0;
                u32 b1;
                u32 b2;
                u32 b3;
                u32 bd = smbase + ((n2*16 + (lane & 7) + ((lane >> 4) & 1)*8)*SW
                                   + colK + ((lane >> 3) & 1)*8)*2;
                ldsm4(b0, b1, b2, b3, bd);
                mma_bf16(c[2*n2][0], c[2*n2][1], c[2*n2][2], c[2*n2][3],
                         aq[0], aq[1], aq[2], aq[3], b0, b1);
                mma_bf16(c[2*n2+1][0], c[2*n2+1][1], c[2*n2+1][2], c[2*n2+1][3],
                         aq[0], aq[1], aq[2], aq[3], b2, b3);
                mma_bf16_k8(c[2*n2][0], c[2*n2][1], c[2*n2][2], c[2*n2][3],
                            a80, a81, kb[2*n2]);
                mma_bf16_k8(c[2*n2+1][0], c[2*n2+1][1], c[2*n2+1][2], c[2*n2+1][3],
                            a80, a81, kb[2*n2+1]);
            }
        }
        int hA = baseA + h;
        int hB = baseB + h;
        #pragma unroll
        for (int f = 0; f < 8; f++) {
            c[f][0] += __ldg(&rpb[hA - 120*f])     + (((mbits >> (f*4+0)) & 1) ? -100.f : 0.f);
            c[f][1] += __ldg(&rpb[hA - 120*f - 8]) + (((mbits >> (f*4+1)) & 1) ? -100.f : 0.f);
            c[f][2] += __ldg(&rpb[hB - 120*f])     + (((mbits >> (f*4+2)) & 1) ? -100.f : 0.f);
            c[f][3] += __ldg(&rpb[hB - 120*f - 8]) + (((mbits >> (f*4+3)) & 1) ? -100.f : 0.f);
        }
        float mx0 = -1e30f;
        float mx1 = -1e30f;
        #pragma unroll
        for (int f = 0; f < 8; f++) {
            mx0 = fmaxf(mx0, fmaxf(c[f][0], c[f][1]));
            mx1 = fmaxf(mx1, fmaxf(c[f][2], c[f][3]));
        }
        mx0 = fmaxf(mx0, __shfl_xor_sync(0xffffffffu, mx0, 1));
        mx0 = fmaxf(mx0, __shfl_xor_sync(0xffffffffu, mx0, 2));
        mx1 = fmaxf(mx1, __shfl_xor_sync(0xffffffffu, mx1, 1));
        mx1 = fmaxf(mx1, __shfl_xor_sync(0xffffffffu, mx1, 2));
        float s0 = 0.f;
        float s1 = 0.f;
        #pragma unroll
        for (int f = 0; f < 8; f++) {
            c[f][0] = __expf(c[f][0] - mx0);
            c[f][1] = __expf(c[f][1] - mx0);
            c[f][2] = __expf(c[f][2] - mx1);
            c[f][3] = __expf(c[f][3] - mx1);
            s0 += c[f][0] + c[f][1];
            s1 += c[f][2] + c[f][3];
        }
        s0 += __shfl_xor_sync(0xffffffffu, s0, 1);
        s0 += __shfl_xor_sync(0xffffffffu, s0, 2);
        s1 += __shfl_xor_sync(0xffffffffu, s1, 1);
        s1 += __shfl_xor_sync(0xffffffffu, s1, 2);
        float inv0 = 1.f / s0;
        float inv1 = 1.f / s1;
        u32 ap[4][4];
        #pragma unroll
        for (int j = 0; j < 4; j++) {
            ap[j][0] = packbf(c[2*j][0]*inv0,   c[2*j][1]*inv0);
            ap[j][1] = packbf(c[2*j][2]*inv1,   c[2*j][3]*inv1);
            ap[j][2] = packbf(c[2*j+1][0]*inv0, c[2*j+1][1]*inv0);
            ap[j][3] = packbf(c[2*j+1][2]*inv1, c[2*j+1][3]*inv1);
        }
        float o[3][4];
        #pragma unroll
        for (int nt = 0; nt < 3; nt++) {
            o[nt][0] = 0.f; o[nt][1] = 0.f; o[nt][2] = 0.f; o[nt][3] = 0.f;
        }
        #pragma unroll
        for (int j = 0; j < 4; j++) {
            u32 lo0; u32 lo1; u32 lo2; u32 lo3;
            u32 hi0; u32 hi1; u32 hi2; u32 hi3;
            u32 vlo = smbase + ((j*16 + (lane & 7))*SW + colV + (lane >> 3)*8)*2;
            u32 vhi = smbase + ((j*16 + 8 + (lane & 7))*SW + colV + (lane >> 3)*8)*2;
            ldsm4t(lo0, lo1, lo2, lo3, vlo);
            ldsm4t(hi0, hi1, hi2, hi3, vhi);
            mma_bf16(o[0][0], o[0][1], o[0][2], o[0][3], ap[j][0], ap[j][1], ap[j][2], ap[j][3], lo0, hi0);
            mma_bf16(o[1][0], o[1][1], o[1][2], o[1][3], ap[j][0], ap[j][1], ap[j][2], ap[j][3], lo1, hi1);
            mma_bf16(o[2][0], o[2][1], o[2][2], o[2][3], ap[j][0], ap[j][1], ap[j][2], ap[j][3], lo2, hi2);
        }
        #pragma unroll
        for (int nt = 0; nt < 3; nt++) {
            int col = h*24 + nt*8 + 2*lc;
            __nv_bfloat162 v0;
            v0.x = __float2bfloat16(o[nt][0]);
            v0.y = __float2bfloat16(o[nt][1]);
            *(__nv_bfloat162*)&g_attnb[(size_t)(pix0 + r0)*C + col] = v0;
            __nv_bfloat162 v1;
            v1.x = __float2bfloat16(o[nt][2]);
            v1.y = __float2bfloat16(o[nt][3]);
            *(__nv_bfloat162*)&g_attnb[(size_t)(pix0 + r1)*C + col] = v1;
        }
    }
}

// ================= K2c: proj GEMM bf16 + bias + residual, 3-stage ==================
__global__ __launch_bounds__(256,2) void k_proj_b(const float* __restrict__ pb) {
    __shared__ __align__(16) __nv_bfloat16 As[3][5120];
    __shared__ __align__(16) __nv_bfloat16 Bs[3][2560];
    int pt = blockIdx.y*128;
    int ct = blockIdx.x*64;
    int tid = threadIdx.x;
    int lane = tid & 31;
    int warp = tid >> 5;
    int m0 = (warp & 3)*32;
    int n0 = (warp >> 2)*32;
    float acc[2][4][4] = {};

    proj_load(As[0], Bs[0], pt, ct, 0, tid);
    proj_load(As[1], Bs[1], pt, ct, 32, tid);

    for (int ch = 0; ch < 6; ch++) {
        cpwait(ch == 5);
        __syncthreads();
        if (ch + 2 < 6) {
            int st = (ch + 2) % 3;
            proj_load(As[st], Bs[st], pt, ct, (ch+2)*32, tid);
        }
        int cb = ch % 3;
        u32 ab = sptr(As[cb]);
        u32 bbs = sptr(Bs[cb]);
        #pragma unroll
        for (int ks = 0; ks < 2; ks++) {
            u32 av[2][4];
            u32 bv[4][2];
            #pragma unroll
            for (int mt = 0; mt < 2; mt++) {
                int row = m0 + mt*16 + (lane & 15);
                u32 ad = ab + (row*40 + ((lane >> 4) & 1)*8 + ks*16)*2;
                ldsm4(av[mt][0], av[mt][1], av[mt][2], av[mt][3], ad);
            }
            #pragma unroll
            for (int n2 = 0; n2 < 2; n2++) {
                int row = n0 + n2*16 + (lane & 7) + ((lane >> 4) & 1)*8;
                u32 ad = bbs + (row*40 + ((lane >> 3) & 1)*8 + ks*16)*2;
                u32 r0;
                u32 r1;
                u32 r2;
                u32 r3;
                ldsm4(r0, r1, r2, r3, ad);
                bv[n2*2+0][0] = r0;
                bv[n2*2+0][1] = r1;
                bv[n2*2+1][0] = r2;
                bv[n2*2+1][1] = r3;
            }
            #pragma unroll
            for (int mt = 0; mt < 2; mt++) {
                #pragma unroll
                for (int nt = 0; nt < 4; nt++) {
                    mma_bf16(acc[mt][nt][0], acc[mt][nt][1], acc[mt][nt][2], acc[mt][nt][3],
                             av[mt][0], av[mt][1], av[mt][2], av[mt][3], bv[nt][0], bv[nt][1]);
                }
            }
        }
    }

    int lr = lane >> 2;
    int lc = lane & 3;
    #pragma unroll
    for (int mt = 0; mt < 2; mt++) {
        #pragma unroll
        for (int half = 0; half < 2; half++) {
            int row = pt + m0 + mt*16 + lr + half*8;
            int bb = row >> 16;
            int widx = (row >> 6) & 1023;
            int tok = row & 63;
            int r = (((widx >> 5) << 3) + (tok >> 3) + SS) & 255;
            int c2 = (((widx & 31) << 3) + (tok & 7) + SS) & 255;
            int gbase = ((bb*HH + r)*WW + c2)*C;
            #pragma unroll
            for (int nt = 0; nt < 4; nt++) {
                int col = ct + n0 + nt*8 + 2*lc;
                float2 v;
                v.x = acc[mt][nt][half*2+0] + pb[col] + g_xt[gbase + col];
                v.y = acc[mt][nt][half*2+1] + pb[col+1] + g_xt[gbase + col + 1];
                *(float2*)&g_x2[gbase + col] = v;
            }
        }
    }
}

// ================= K3: LN2 -> bf16 ==================
__global__ __launch_bounds__(256) void k_ln2(const float* __restrict__ w,
                                             const float* __restrict__ b) {
    int pix = blockIdx.x*8 + (threadIdx.x >> 5);
    int lane = threadIdx.x & 31;
    const float* row = g_x2 + (size_t)pix*C;
    float v[6];
    float sum = 0.f;
    float sq = 0.f;
    #pragma unroll
    for (int i = 0; i < 6; i++) {
        v[i] = row[lane + 32*i];
        sum += v[i];
        sq += v[i]*v[i];
    }
    #pragma unroll
    for (int o = 16; o; o >>= 1) {
        sum += __shfl_xor_sync(0xffffffffu, sum, o);
        sq  += __shfl_xor_sync(0xffffffffu, sq, o);
    }
    float mu = sum / C;
    float rv = rsqrtf(sq / C - mu*mu + 1e-5f);
    __nv_bfloat16* outp = g_ynb + (size_t)pix*C;
    #pragma unroll
    for (int i = 0; i < 6; i++) {
        int c = lane + 32*i;
        outp[c] = __float2bfloat16((v[i]-mu)*rv*w[c] + b[c]);
    }
}

// ================= K4: pin GEMM bf16 (131072 x 1020 x 192), 3-stage ==================
__global__ __launch_bounds__(256,2) void k_pin_b() {
    extern __shared__ __nv_bfloat16 smp[];
    __nv_bfloat16* As = smp;           // 3 x 5120
    __nv_bfloat16* Bs = smp + 15360;   // 3 x 5120
    int pt = blockIdx.y*128;
    int ot = blockIdx.x*128;
    int tid = threadIdx.x;
    int lane = tid & 31;
    int warp = tid >> 5;
    int m0 = (warp >> 2)*64;
    int n0 = (warp & 3)*32;
    float acc[4][4][4] = {};

    pin_load(As, Bs, pt, ot, 0, tid);
    pin_load(As + 5120, Bs + 5120, pt, ot, 32, tid);

    for (int ch = 0; ch < 6; ch++) {
        cpwait(ch == 5);
        __syncthreads();
        if (ch + 2 < 6) {
            int st = (ch + 2) % 3;
            pin_load(As + st*5120, Bs + st*5120, pt, ot, (ch+2)*32, tid);
        }
        int cb = ch % 3;
        u32 ab = sptr(As + cb*5120);
        u32 bbs = sptr(Bs + cb*5120);
        #pragma unroll
        for (int ks = 0; ks < 2; ks++) {
            u32 av[4][4];
            u32 bv[4][2];
            #pragma unroll
            for (int mt = 0; mt < 4; mt++) {
                int row = m0 + mt*16 + (lane & 15);
                u32 ad = ab + (row*40 + ((lane >> 4) & 1)*8 + ks*16)*2;
                ldsm4(av[mt][0], av[mt][1], av[mt][2], av[mt][3], ad);
            }
            #pragma unroll
            for (int n2 = 0; n2 < 2; n2++) {
                int row = n0 + n2*16 + (lane & 7) + ((lane >> 4) & 1)*8;
                u32 ad = bbs + (row*40 + ((lane >> 3) & 1)*8 + ks*16)*2;
                u32 r0;
                u32 r1;
                u32 r2;
                u32 r3;
                ldsm4(r0, r1, r2, r3, ad);
                bv[n2*2+0][0] = r0;
                bv[n2*2+0][1] = r1;
                bv[n2*2+1][0] = r2;
                bv[n2*2+1][1] = r3;
            }
            #pragma unroll
            for (int mt = 0; mt < 4; mt++) {
                #pragma unroll
                for (int nt = 0; nt < 4; nt++) {
                    mma_bf16(acc[mt][nt][0], acc[mt][nt][1], acc[mt][nt][2], acc[mt][nt][3],
                             av[mt][0], av[mt][1], av[mt][2], av[mt][3], bv[nt][0], bv[nt][1]);
                }
            }
        }
    }

    int lr = lane >> 2;
    int lc = lane & 3;
    #pragma unroll
    for (int mt = 0; mt < 4; mt++) {
        int row = pt + m0 + mt*16 + lr;
        #pragma unroll
        for (int nt = 0; nt < 4; nt++) {
            int col = ot + n0 + nt*8 + 2*lc;
            if (col < HID2) {
                __nv_bfloat162 v0;
                v0.x = __float2bfloat16(acc[mt][nt][0]);
                v0.y = __float2bfloat16(acc[mt][nt][1]);
                *(__nv_bfloat162*)&g_y[(size_t)row*HID2 + col] = v0;
                __nv_bfloat162 v1;
                v1.x = __float2bfloat16(acc[mt][nt][2]);
                v1.y = __float2bfloat16(acc[mt][nt][3]);
                *(__nv_bfloat162*)&g_y[(size_t)(row+8)*HID2 + col] = v1;
            }
        }
    }
}

// ================= K5: depthwise 3x3 + gated GELU (f32x2 packed FMA) ==================
__global__ __launch_bounds__(256) void k_dw2(const float* __restrict__ dw) {
    int bx = blockIdx.x;
    int t = threadIdx.x;
    int xseg = (bx & 63) * 4;
    int r = (bx >> 6) & 255;
    int bb = bx >> 14;
    size_t prow = (size_t)(bb*HH + r)*WW;
    if (t >= 255) {
        if (t == 255) {
            #pragma unroll
            for (int o = 0; o < 4; o++) {
                *(u32*)&g_gg[(prow + xseg + o)*512 + 510] = 0u;
            }
        }
        return;
    }
    int c = t*2;
    u64 ya[3][6];
    u64 yb[3][6];
    #pragma unroll
    for (int dy = 0; dy < 3; dy++) {
        int rowi = r + dy - 1;
        bool rok = (unsigned)rowi < 256u;
        #pragma unroll
        for (int dx = 0; dx < 6; dx++) {
            int col = xseg + dx - 1;
            bool ok = rok && ((unsigned)col < 256u);
            float2 va = make_float2(0.f, 0.f);
            float2 vb = make_float2(0.f, 0.f);
            if (ok) {
                size_t base = ((size_t)(bb*HH + rowi)*WW + col)*HID2;
                va = __bfloat1622float2(*(const __nv_bfloat162*)&g_y[base + c]);
                vb = __bfloat1622float2(*(const __nv_bfloat162*)&g_y[base + c + HID]);
            }
            ya[dy][dx] = pk2(va.x, va.y);
            yb[dy][dx] = pk2(vb.x, vb.y);
        }
    }
    u64 wA[9];
    u64 wB[9];
    #pragma unroll
    for (int q = 0; q < 9; q++) {
        wA[q] = pk2(dw[c*9 + q], dw[(c+1)*9 + q]);
        wB[q] = pk2(dw[(c+HID)*9 + q], dw[(c+HID+1)*9 + q]);
    }
    const u64 zero2 = pk2(0.f, 0.f);
    #pragma unroll
    for (int o = 0; o < 4; o++) {
        u64 sa = zero2;
        u64 sb = zero2;
        #pragma unroll
        for (int ky = 0; ky < 3; ky++) {
            #pragma unroll
            for (int kx = 0; kx < 3; kx++) {
                int q = ky*3 + kx;
                sa = fma2(wA[q], ya[ky][o+kx], sa);
                sb = fma2(wB[q], yb[ky][o+kx], sb);
            }
        }
        float s0;
        float s1;
        upk2(s0, s1, sa);
        float g0;
        float g1;
        upk2(g0, g1, sb);
        float e0 = 0.5f*s0*(1.f + erff(s0*0.70710678118654752f)) * g0;
        float e1 = 0.5f*s1*(1.f + erff(s1*0.70710678118654752f)) * g1;
        *(__nv_bfloat162*)&g_gg[(prow + xseg + o)*512 + c] = __floats2bfloat162_rn(e0, e1);
    }
}

// ================= K6: pout GEMM bf16 + residual -> NCHW, 3-stage ==================
#define SPP 132
__global__ __launch_bounds__(256,2) void k_pout_b(float* __restrict__ outp) {
    __shared__ __align__(16) char smraw[46080];
    __nv_bfloat16* As = (__nv_bfloat16*)smraw;            // 3 x 5120
    __nv_bfloat16* Bs = (__nv_bfloat16*)smraw + 15360;    // 3 x 2560
    float* Cs = (float*)smraw;                            // 8448 floats (33792 B)
    int pt = blockIdx.y*128;
    int ct = blockIdx.x*64;
    int tid = threadIdx.x;
    int lane = tid & 31;
    int warp = tid >> 5;
    int m0 = (warp & 3)*32;
    int n0 = (warp >> 2)*32;
    float acc[2][4][4] = {};

    pout_load(As, Bs, pt, ct, 0, tid);
    pout_load(As + 5120, Bs + 2560, pt, ct, 32, tid);

    for (int ch = 0; ch < 16; ch++) {
        cpwait(ch == 15);
        __syncthreads();
        if (ch + 2 < 16) {
            int st = (ch + 2) % 3;
            pout_load(As + st*5120, Bs + st*2560, pt, ct, (ch+2)*32, tid);
        }
        int cb = ch % 3;
        u32 ab = sptr(As + cb*5120);
        u32 bbs = sptr(Bs + cb*2560);
        #pragma unroll
        for (int ks = 0; ks < 2; ks++) {
            u32 av[2][4];
            u32 bv[4][2];
            #pragma unroll
            for (int mt = 0; mt < 2; mt++) {
                int row = m0 + mt*16 + (lane & 15);
                u32 ad = ab + (row*40 + ((lane >> 4) & 1)*8 + ks*16)*2;
                ldsm4(av[mt][0], av[mt][1], av[mt][2], av[mt][3], ad);
            }
            #pragma unroll
            for (int n2 = 0; n2 < 2; n2++) {
                int row = n0 + n2*16 + (lane & 7) + ((lane >> 4) & 1)*8;
                u32 ad = bbs + (row*40 + ((lane >> 3) & 1)*8 + ks*16)*2;
                u32 r0;
                u32 r1;
                u32 r2;
                u32 r3;
                ldsm4(r0, r1, r2, r3, ad);
                bv[n2*2+0][0] = r0;
                bv[n2*2+0][1] = r1;
                bv[n2*2+1][0] = r2;
                bv[n2*2+1][1] = r3;
            }
            #pragma unroll
            for (int mt = 0; mt < 2; mt++) {
                #pragma unroll
                for (int nt = 0; nt < 4; nt++) {
                    mma_bf16(acc[mt][nt][0], acc[mt][nt][1], acc[mt][nt][2], acc[mt][nt][3],
                             av[mt][0], av[mt][1], av[mt][2], av[mt][3], bv[nt][0], bv[nt][1]);
                }
            }
        }
    }
    __syncthreads();

    int lr = lane >> 2;
    int lc = lane & 3;
    #pragma unroll
    for (int mt = 0; mt < 2; mt++) {
        int row = m0 + mt*16 + lr;
        #pragma unroll
        for (int nt = 0; nt < 4; nt++) {
            int col = n0 + nt*8 + 2*lc;
            Cs[col*SPP + row] = acc[mt][nt][0];
            Cs[(col+1)*SPP + row] = acc[mt][nt][1];
            Cs[col*SPP + row + 8] = acc[mt][nt][2];
            Cs[(col+1)*SPP + row + 8] = acc[mt][nt][3];
        }
    }
    __syncthreads();
    for (int e = tid; e < 2048; e += 256) {
        int p = e >> 4;
        int c4 = e & 15;
        float4 v = *(const float4*)&g_x2[(size_t)(pt + p)*C + ct + c4*4];
        Cs[(c4*4+0)*SPP + p] += v.x;
        Cs[(c4*4+1)*SPP + p] += v.y;
        Cs[(c4*4+2)*SPP + p] += v.z;
        Cs[(c4*4+3)*SPP + p] += v.w;
    }
    __syncthreads();
    int bb = pt >> 16;
    int hw0 = pt & 65535;
    for (int e = tid; e < 2048; e += 256) {
        int c = e >> 5;
        int p4 = e & 31;
        float4 v = *(const float4*)&Cs[c*SPP + p4*4];
        *(float4*)&outp[((size_t)(bb*C + ct + c))*HW + hw0 + p4*4] = v;
    }
}

// ================= launch ==================
extern "C" void kernel_launch(void* const* d_in, const int* in_sizes, int n_in,
                              void* d_out, int out_size) {
    const float* x      = (const float*)d_in[0];
    const float* n1w    = (const float*)d_in[1];
    const float* n1b    = (const float*)d_in[2];
    const float* qkv_w  = (const float*)d_in[3];
    const float* rpb    = (const float*)d_in[4];
    const float* proj_w = (const float*)d_in[5];
    const float* proj_b = (const float*)d_in[6];
    const float* n2w    = (const float*)d_in[7];
    const float* n2b    = (const float*)d_in[8];
    const float* pin_w  = (const float*)d_in[9];
    const float* dw_w   = (const float*)d_in[10];
    const float* pout_w = (const float*)d_in[11];
    float* outp = (float*)d_out;

    const int wattn_smem = 64*SW*2;        // 74752
    const int gemm3_smem = 6*5120*2;       // 61440
    cudaFuncSetAttribute(k_wattn_t, cudaFuncAttributeMaxDynamicSharedMemorySize, wattn_smem);
    cudaFuncSetAttribute(k_qkv_b, cudaFuncAttributeMaxDynamicSharedMemorySize, gemm3_smem);
    cudaFuncSetAttribute(k_pin_b, cudaFuncAttributeMaxDynamicSharedMemorySize, gemm3_smem);

    const int cvt_total = 576*C + C*C + HID2*C + C*512;
    k_cvt_all<<<(cvt_total + 255)/256, 256>>>(qkv_w, proj_w, pin_w, pout_w);
    k_ln1    <<<NPIX/32, 256>>>(x, n1w, n1b);
    k_qkv_b  <<<dim3(5, NPIX/128), 256, gemm3_smem>>>();
    k_wattn_t<<<2048, 128, wattn_smem>>>(rpb);
    k_proj_b <<<dim3(3, NPIX/128), 256>>>(proj_b);
    k_ln2    <<<NPIX/8, 256>>>(n2w, n2b);
    k_pin_b  <<<dim3(8, NPIX/128), 256, gemm3_smem>>>();
    k_dw2    <<<BATCH*HH*(WW/4), 256>>>(dw_w);
    k_pout_b <<<dim3(3, NPIX/128), 256>>>(outp);
}